// round 1
// baseline (speedup 1.0000x reference)
#include <cuda_runtime.h>
#include <cuda_bf16.h>
#include <math.h>

// Problem constants
#define B_   256
#define S_   128
#define P_   100
#define N_   500
#define E_   256
#define H_   4
#define HD_  64
#define L_   2
#define F_   1024
#define T_   (B_ * S_)      // 32768 tokens
#define NT_  (P_ + N_)      // 600 targets per sample

// ---------------------------------------------------------------------------
// Scratch (device globals — no allocation allowed)
// ---------------------------------------------------------------------------
__device__ float g_x   [(size_t)T_ * E_];       // activations [32768,256]
__device__ float g_qkv [(size_t)T_ * 3 * E_];   // [32768,768]
__device__ float g_attn[(size_t)T_ * E_];       // attention output pre-proj
__device__ float g_tmp [(size_t)T_ * E_];       // gemm output before LN
__device__ float g_ff  [(size_t)T_ * F_];       // [32768,1024]
__device__ float g_out [(size_t)B_ * 3 * E_];   // concat(user, attr_x, item)
__device__ float g_wu  [B_];                    // sigmoid gate per sample

// ---------------------------------------------------------------------------
// Embedding gather: x[t,e] = attr_emb[attr[t], e]
// ---------------------------------------------------------------------------
__global__ void gather_kernel(const int* __restrict__ attr,
                              const float* __restrict__ emb,
                              float* __restrict__ x) {
    size_t i = (size_t)blockIdx.x * blockDim.x + threadIdx.x;
    if (i < (size_t)T_ * E_) {
        int t = (int)(i >> 8);
        int e = (int)(i & (E_ - 1));
        x[i] = emb[(size_t)attr[t] * E_ + e];
    }
}

// ---------------------------------------------------------------------------
// SGEMM: C[M,N] = A[M,K] @ B[N,K]^T + bias[N]  (optional ReLU)
// 64x64 tile, BK=16, 256 threads, 4x4 microtile per thread.
// Requires M%64==0, N%64==0, K%16==0 (holds for all calls here).
// ---------------------------------------------------------------------------
template<bool RELU>
__global__ __launch_bounds__(256)
void sgemm_bt(const float* __restrict__ A, const float* __restrict__ Bm,
              const float* __restrict__ bias, float* __restrict__ C,
              int M, int N, int K) {
    __shared__ float As[16][65];
    __shared__ float Bs[16][65];
    const int bm = blockIdx.y * 64;
    const int bn = blockIdx.x * 64;
    const int t  = threadIdx.x;
    const int tx = t & 15;        // 0..15  -> n
    const int ty = t >> 4;        // 0..15  -> m
    const int lr = t >> 2;        // 0..63  load row
    const int lc = (t & 3) * 4;   // 0,4,8,12 load col (k)

    float acc[4][4];
#pragma unroll
    for (int i = 0; i < 4; i++)
#pragma unroll
        for (int j = 0; j < 4; j++) acc[i][j] = 0.f;

    for (int k0 = 0; k0 < K; k0 += 16) {
        float4 a4 = *(const float4*)(A  + (size_t)(bm + lr) * K + k0 + lc);
        float4 b4 = *(const float4*)(Bm + (size_t)(bn + lr) * K + k0 + lc);
        As[lc + 0][lr] = a4.x; As[lc + 1][lr] = a4.y;
        As[lc + 2][lr] = a4.z; As[lc + 3][lr] = a4.w;
        Bs[lc + 0][lr] = b4.x; Bs[lc + 1][lr] = b4.y;
        Bs[lc + 2][lr] = b4.z; Bs[lc + 3][lr] = b4.w;
        __syncthreads();
#pragma unroll
        for (int k = 0; k < 16; k++) {
            float ar[4], br[4];
#pragma unroll
            for (int i = 0; i < 4; i++) ar[i] = As[k][ty * 4 + i];
#pragma unroll
            for (int j = 0; j < 4; j++) br[j] = Bs[k][tx * 4 + j];
#pragma unroll
            for (int i = 0; i < 4; i++)
#pragma unroll
                for (int j = 0; j < 4; j++) acc[i][j] += ar[i] * br[j];
        }
        __syncthreads();
    }

#pragma unroll
    for (int i = 0; i < 4; i++) {
        const int row = bm + ty * 4 + i;
#pragma unroll
        for (int j = 0; j < 4; j++) {
            const int col = bn + tx * 4 + j;
            float v = acc[i][j] + bias[col];
            if (RELU) v = fmaxf(v, 0.f);
            C[(size_t)row * N + col] = v;
        }
    }
}

// ---------------------------------------------------------------------------
// Attention: one block per (b,h); thread = query row. K,V tiles in smem.
// qkv layout: [t, 768] with q:[0,256) k:[256,512) v:[512,768); head h at h*64.
// ---------------------------------------------------------------------------
__global__ __launch_bounds__(128)
void attn_kernel(const float* __restrict__ qkv,
                 const int* __restrict__ lens,
                 float* __restrict__ out) {
    const int bh = blockIdx.x;
    const int b  = bh / H_;
    const int h  = bh % H_;
    extern __shared__ float sm[];
    float* Ks = sm;                // [128][64]
    float* Vs = sm + S_ * HD_;     // [128][64]

    for (int i = threadIdx.x; i < S_ * HD_; i += blockDim.x) {
        const int s = i >> 6, d = i & 63;
        const size_t base = (size_t)(b * S_ + s) * (3 * E_) + h * HD_;
        Ks[i] = qkv[base + E_     + d];
        Vs[i] = qkv[base + 2 * E_ + d];
    }
    __syncthreads();

    const int q   = threadIdx.x;
    const int len = lens[b];

    float4 qr[16];
    {
        const float4* qp = (const float4*)(qkv + (size_t)(b * S_ + q) * (3 * E_) + h * HD_);
#pragma unroll
        for (int d = 0; d < 16; d++) qr[d] = qp[d];
    }

    float sc[S_];
    float mx = -3.0e38f;
    for (int k = 0; k < S_; k++) {
        const float4* kp = (const float4*)(Ks + k * HD_);
        float s_ = 0.f;
#pragma unroll
        for (int d = 0; d < 16; d++) {
            float4 kk = kp[d];
            s_ += qr[d].x * kk.x + qr[d].y * kk.y + qr[d].z * kk.z + qr[d].w * kk.w;
        }
        s_ *= 0.125f;                     // 1/sqrt(64)
        if (k >= len) s_ -= 1e9f;
        sc[k] = s_;
        mx = fmaxf(mx, s_);
    }
    float sum = 0.f;
    for (int k = 0; k < S_; k++) {
        float e = expf(sc[k] - mx);
        sc[k] = e;
        sum += e;
    }
    const float inv = 1.f / sum;

    float4 acc[16];
#pragma unroll
    for (int d = 0; d < 16; d++) acc[d] = make_float4(0.f, 0.f, 0.f, 0.f);
    for (int k = 0; k < S_; k++) {
        const float p = sc[k] * inv;
        const float4* vp = (const float4*)(Vs + k * HD_);
#pragma unroll
        for (int d = 0; d < 16; d++) {
            float4 vv = vp[d];
            acc[d].x += p * vv.x; acc[d].y += p * vv.y;
            acc[d].z += p * vv.z; acc[d].w += p * vv.w;
        }
    }
    float4* op = (float4*)(out + (size_t)(b * S_ + q) * E_ + h * HD_);
#pragma unroll
    for (int d = 0; d < 16; d++) op[d] = acc[d];
}

// ---------------------------------------------------------------------------
// Fused residual add + LayerNorm: out = LN(x + y) * s + b  (in-place safe)
// One block per token, 256 threads.
// ---------------------------------------------------------------------------
__global__ __launch_bounds__(256)
void add_ln_kernel(const float* __restrict__ x, const float* __restrict__ y,
                   const float* __restrict__ sc, const float* __restrict__ bi,
                   float* __restrict__ out) {
    const int t = blockIdx.x;
    const int e = threadIdx.x;
    const size_t idx = (size_t)t * E_ + e;
    float v = x[idx] + y[idx];

    __shared__ float red[E_];
    __shared__ float stat;
    red[e] = v;
    __syncthreads();
    for (int o = 128; o; o >>= 1) { if (e < o) red[e] += red[e + o]; __syncthreads(); }
    if (e == 0) stat = red[0] * (1.f / E_);
    __syncthreads();
    const float m = stat;
    const float d = v - m;
    __syncthreads();
    red[e] = d * d;
    __syncthreads();
    for (int o = 128; o; o >>= 1) { if (e < o) red[e] += red[e + o]; __syncthreads(); }
    if (e == 0) stat = red[0] * (1.f / E_);
    __syncthreads();
    out[idx] = d * rsqrtf(stat + 1e-5f) * sc[e] + bi[e];
}

// ---------------------------------------------------------------------------
// Per-sample sigmoid gate: wu[b] = sigmoid(attr_feat[b,:] . fw_W + fw_b)
// ---------------------------------------------------------------------------
__global__ void wu_kernel(const float* __restrict__ feat,
                          const float* __restrict__ W,
                          const float* __restrict__ bias,
                          float* __restrict__ wu) {
    const int b = blockIdx.x * blockDim.x + threadIdx.x;
    if (b < B_) {
        float z = bias[0];
#pragma unroll
        for (int i = 0; i < 13; i++) z += feat[b * 13 + i] * W[i];
        wu[b] = 1.f / (1.f + expf(-z));
    }
}

// ---------------------------------------------------------------------------
// Weighted pool + concat: out[b] = [user_emb | sum_s w(b,s) x(b,s,:) | item_emb]
// ---------------------------------------------------------------------------
__global__ __launch_bounds__(256)
void pool_kernel(const float* __restrict__ x, const float* __restrict__ attr_tf,
                 const int* __restrict__ lens, const int* __restrict__ lens_user,
                 const float* __restrict__ wu,
                 const int* __restrict__ user_ids, const int* __restrict__ item_ids,
                 const float* __restrict__ user_emb, const float* __restrict__ item_emb,
                 float* __restrict__ out) {
    const int b = blockIdx.x;
    const int e = threadIdx.x;
    __shared__ float w[S_];
    if (e < S_) {
        const int s = e;
        float wgt = 0.f;
        if (s < lens[b]) {
            const float g = (s < lens_user[b]) ? wu[b] : (1.f - wu[b]);
            wgt = attr_tf[b * S_ + s] * g;
        }
        w[s] = wgt;
    }
    __syncthreads();
    float acc = 0.f;
    const float* xb = x + (size_t)b * S_ * E_ + e;
    for (int s = 0; s < S_; s++) acc += w[s] * xb[(size_t)s * E_];
    out[(size_t)b * 3 * E_ + E_ + e]     = acc;
    out[(size_t)b * 3 * E_ + e]          = user_emb[(size_t)user_ids[b] * E_ + e];
    out[(size_t)b * 3 * E_ + 2 * E_ + e] = item_emb[(size_t)item_ids[b] * E_ + e];
}

// ---------------------------------------------------------------------------
// Scoring head: one warp per (b, target). Writes logits, mask, new_targets.
// ---------------------------------------------------------------------------
__global__ __launch_bounds__(256)
void logits_kernel(const float* __restrict__ outv, const float* __restrict__ out_emb,
                   const int* __restrict__ pos_t, const int* __restrict__ pos_l,
                   const int* __restrict__ neg_t, const int* __restrict__ neg_l,
                   float* __restrict__ dout) {
    const int gw   = (int)((blockIdx.x * blockDim.x + threadIdx.x) >> 5);
    const int lane = threadIdx.x & 31;
    if (gw >= B_ * NT_) return;
    const int b = gw / NT_;
    const int j = gw % NT_;
    int tgt; float valid, is_pos;
    if (j < P_) {
        tgt = pos_t[b * P_ + j];
        valid = (j < pos_l[b]) ? 1.f : 0.f;
        is_pos = 1.f;
    } else {
        const int jn = j - P_;
        tgt = neg_t[b * N_ + jn];
        valid = (jn < neg_l[b]) ? 1.f : 0.f;
        is_pos = 0.f;
    }
    const float* er = out_emb + (size_t)tgt * (3 * E_);
    const float* ov = outv + (size_t)b * (3 * E_);
    float acc = 0.f;
    for (int k = lane; k < 3 * E_; k += 32) acc += er[k] * ov[k];
#pragma unroll
    for (int o = 16; o; o >>= 1) acc += __shfl_xor_sync(0xffffffffu, acc, o);
    if (lane == 0) {
        const int idx = b * NT_ + j;
        dout[idx]                 = acc;
        dout[B_ * NT_ + idx]      = valid;
        dout[2 * B_ * NT_ + idx]  = is_pos * valid;
    }
}

// ---------------------------------------------------------------------------
// Launch
// ---------------------------------------------------------------------------
extern "C" void kernel_launch(void* const* d_in, const int* in_sizes, int n_in,
                              void* d_out, int out_size) {
    // Input unpack (metadata order = setup_inputs dict order)
    const int*   attr           = (const int*)  d_in[0];
    // d_in[1] = attr_inds (unused by reference)
    const float* attr_tf        = (const float*)d_in[2];
    const float* attr_feat      = (const float*)d_in[3];
    const int*   attr_lens      = (const int*)  d_in[4];
    const int*   attr_lens_user = (const int*)  d_in[5];
    // d_in[6] = attr_lens_item (unused)
    const int*   user_ids       = (const int*)  d_in[7];
    const int*   item_ids       = (const int*)  d_in[8];
    const int*   pos_targets    = (const int*)  d_in[9];
    const int*   pos_lens       = (const int*)  d_in[10];
    const int*   neg_targets    = (const int*)  d_in[11];
    const int*   neg_lens       = (const int*)  d_in[12];
    const float* attr_emb       = (const float*)d_in[13];
    const float* user_emb       = (const float*)d_in[14];
    const float* item_emb       = (const float*)d_in[15];
    const float* out_emb        = (const float*)d_in[16];
    const float* fw_W           = (const float*)d_in[17];
    const float* fw_b           = (const float*)d_in[18];
    const float* qkv_w          = (const float*)d_in[19];
    const float* qkv_b          = (const float*)d_in[20];
    const float* attn_out_w     = (const float*)d_in[21];
    const float* attn_out_b     = (const float*)d_in[22];
    const float* ln1_s          = (const float*)d_in[23];
    const float* ln1_b          = (const float*)d_in[24];
    const float* ff1_w          = (const float*)d_in[25];
    const float* ff1_b          = (const float*)d_in[26];
    const float* ff2_w          = (const float*)d_in[27];
    const float* ff2_b          = (const float*)d_in[28];
    const float* ln2_s          = (const float*)d_in[29];
    const float* ln2_b          = (const float*)d_in[30];

    float *x, *qkv, *attn, *tmp, *ff, *outv, *wu;
    cudaGetSymbolAddress((void**)&x,    g_x);
    cudaGetSymbolAddress((void**)&qkv,  g_qkv);
    cudaGetSymbolAddress((void**)&attn, g_attn);
    cudaGetSymbolAddress((void**)&tmp,  g_tmp);
    cudaGetSymbolAddress((void**)&ff,   g_ff);
    cudaGetSymbolAddress((void**)&outv, g_out);
    cudaGetSymbolAddress((void**)&wu,   g_wu);

    const int attn_smem = 2 * S_ * HD_ * (int)sizeof(float);  // 64 KB
    cudaFuncSetAttribute(attn_kernel, cudaFuncAttributeMaxDynamicSharedMemorySize,
                         attn_smem);

    // x = attr_emb[attr]
    gather_kernel<<<T_, 256>>>(attr, attr_emb, x);

    for (int l = 0; l < L_; l++) {
        const float* lqkv_w = qkv_w      + (size_t)l * 3 * E_ * E_;
        const float* lqkv_b = qkv_b      + (size_t)l * 3 * E_;
        const float* lao_w  = attn_out_w + (size_t)l * E_ * E_;
        const float* lao_b  = attn_out_b + (size_t)l * E_;
        const float* l1s    = ln1_s + (size_t)l * E_;
        const float* l1b    = ln1_b + (size_t)l * E_;
        const float* lf1_w  = ff1_w + (size_t)l * F_ * E_;
        const float* lf1_b  = ff1_b + (size_t)l * F_;
        const float* lf2_w  = ff2_w + (size_t)l * E_ * F_;
        const float* lf2_b  = ff2_b + (size_t)l * E_;
        const float* l2s    = ln2_s + (size_t)l * E_;
        const float* l2b    = ln2_b + (size_t)l * E_;

        // QKV: [32768,256] @ [768,256]^T
        sgemm_bt<false><<<dim3(3 * E_ / 64, T_ / 64), 256>>>(
            x, lqkv_w, lqkv_b, qkv, T_, 3 * E_, E_);
        // attention
        attn_kernel<<<B_ * H_, S_, attn_smem>>>(qkv, attr_lens, attn);
        // proj: [32768,256] @ [256,256]^T
        sgemm_bt<false><<<dim3(E_ / 64, T_ / 64), 256>>>(
            attn, lao_w, lao_b, tmp, T_, E_, E_);
        add_ln_kernel<<<T_, E_>>>(x, tmp, l1s, l1b, x);
        // FF1 (+ReLU): [32768,1024]
        sgemm_bt<true><<<dim3(F_ / 64, T_ / 64), 256>>>(
            x, lf1_w, lf1_b, ff, T_, F_, E_);
        // FF2
        sgemm_bt<false><<<dim3(E_ / 64, T_ / 64), 256>>>(
            ff, lf2_w, lf2_b, tmp, T_, E_, F_);
        add_ln_kernel<<<T_, E_>>>(x, tmp, l2s, l2b, x);
    }

    wu_kernel<<<1, 256>>>(attr_feat, fw_W, fw_b, wu);
    pool_kernel<<<B_, 256>>>(x, attr_tf, attr_lens, attr_lens_user, wu,
                             user_ids, item_ids, user_emb, item_emb, outv);

    const int nwarps = B_ * NT_;                     // 153600
    logits_kernel<<<(nwarps * 32 + 255) / 256, 256>>>(
        outv, out_emb, pos_targets, pos_lens, neg_targets, neg_lens,
        (float*)d_out);
}

// round 2
// speedup vs baseline: 1.5586x; 1.5586x over previous
#include <cuda_runtime.h>
#include <cuda_bf16.h>
#include <math.h>

// Problem constants
#define B_   256
#define S_   128
#define P_   100
#define N_   500
#define E_   256
#define H_   4
#define HD_  64
#define L_   2
#define F_   1024
#define T_   (B_ * S_)      // 32768 tokens
#define NT_  (P_ + N_)      // 600 targets per sample

// ---------------------------------------------------------------------------
// Scratch (device globals — no allocation allowed)
// ---------------------------------------------------------------------------
__device__ float g_x   [(size_t)T_ * E_];       // activations [32768,256]
__device__ float g_qkv [(size_t)T_ * 3 * E_];   // [32768,768]
__device__ float g_attn[(size_t)T_ * E_];       // attention output pre-proj
__device__ float g_tmp [(size_t)T_ * E_];       // gemm output before LN
__device__ float g_ff  [(size_t)T_ * F_];       // [32768,1024]
__device__ float g_out [(size_t)B_ * 3 * E_];   // concat(user, attr_x, item)
__device__ float g_wu  [B_];                    // sigmoid gate per sample

// ---------------------------------------------------------------------------
// Embedding gather: x[t,e] = attr_emb[attr[t], e]
// ---------------------------------------------------------------------------
__global__ void gather_kernel(const int* __restrict__ attr,
                              const float* __restrict__ emb,
                              float* __restrict__ x) {
    size_t i = (size_t)blockIdx.x * blockDim.x + threadIdx.x;
    if (i < (size_t)T_ * E_) {
        int t = (int)(i >> 8);
        int e = (int)(i & (E_ - 1));
        x[i] = emb[(size_t)attr[t] * E_ + e];
    }
}

// ---------------------------------------------------------------------------
// SGEMM: C[M,N] = A[M,K] @ B[N,K]^T + bias[N]  (optional ReLU)
// 128x128 tile, BK=16, 256 threads, 8x8 microtile (split halves), double-
// buffered smem with register staging. Requires M%128==0, N%128==0, K%16==0.
// ---------------------------------------------------------------------------
#define SPAD 132   // 128 + 4 pad (keeps float4 alignment: 132*4 % 16 == 0)

template<bool RELU>
__global__ __launch_bounds__(256, 2)
void sgemm128(const float* __restrict__ A, const float* __restrict__ Bm,
              const float* __restrict__ bias, float* __restrict__ C,
              int M, int N, int K) {
    __shared__ float As[2][16][SPAD];
    __shared__ float Bs[2][16][SPAD];

    const int bm = blockIdx.y * 128;
    const int bn = blockIdx.x * 128;
    const int t  = threadIdx.x;
    const int tx = t & 15;        // 0..15 -> n quad
    const int ty = t >> 4;        // 0..15 -> m quad
    const int lr = t >> 2;        // 0..63  staged load row
    const int lc = (t & 3) * 4;   // 0,4,8,12 staged load col (k)

    const float* Ap0 = A  + (size_t)(bm + lr)      * K + lc;
    const float* Ap1 = A  + (size_t)(bm + lr + 64) * K + lc;
    const float* Bp0 = Bm + (size_t)(bn + lr)      * K + lc;
    const float* Bp1 = Bm + (size_t)(bn + lr + 64) * K + lc;

    float acc[8][8];
#pragma unroll
    for (int i = 0; i < 8; i++)
#pragma unroll
        for (int j = 0; j < 8; j++) acc[i][j] = 0.f;

    float4 ra0, ra1, rb0, rb1;

    // prologue: stage 0
    ra0 = *(const float4*)(Ap0);
    ra1 = *(const float4*)(Ap1);
    rb0 = *(const float4*)(Bp0);
    rb1 = *(const float4*)(Bp1);
    {
        const float av0[4] = {ra0.x, ra0.y, ra0.z, ra0.w};
        const float av1[4] = {ra1.x, ra1.y, ra1.z, ra1.w};
        const float bv0[4] = {rb0.x, rb0.y, rb0.z, rb0.w};
        const float bv1[4] = {rb1.x, rb1.y, rb1.z, rb1.w};
#pragma unroll
        for (int j = 0; j < 4; j++) {
            As[0][lc + j][lr]      = av0[j];
            As[0][lc + j][lr + 64] = av1[j];
            Bs[0][lc + j][lr]      = bv0[j];
            Bs[0][lc + j][lr + 64] = bv1[j];
        }
    }
    __syncthreads();

    const int nk = K >> 4;
    for (int it = 0; it < nk; it++) {
        const int cur = it & 1;
        const bool more = (it + 1 < nk);
        if (more) {
            const int k0 = (it + 1) << 4;
            ra0 = *(const float4*)(Ap0 + k0);
            ra1 = *(const float4*)(Ap1 + k0);
            rb0 = *(const float4*)(Bp0 + k0);
            rb1 = *(const float4*)(Bp1 + k0);
        }
#pragma unroll
        for (int k = 0; k < 16; k++) {
            const float4 a0 = *(const float4*)&As[cur][k][ty * 4];
            const float4 a1 = *(const float4*)&As[cur][k][ty * 4 + 64];
            const float4 b0 = *(const float4*)&Bs[cur][k][tx * 4];
            const float4 b1 = *(const float4*)&Bs[cur][k][tx * 4 + 64];
            const float av[8] = {a0.x, a0.y, a0.z, a0.w, a1.x, a1.y, a1.z, a1.w};
            const float bv[8] = {b0.x, b0.y, b0.z, b0.w, b1.x, b1.y, b1.z, b1.w};
#pragma unroll
            for (int i = 0; i < 8; i++)
#pragma unroll
                for (int j = 0; j < 8; j++) acc[i][j] += av[i] * bv[j];
        }
        if (more) {
            __syncthreads();   // everyone done reading buffer cur^1 (read 2 its ago)
            const int nxt = cur ^ 1;
            const float av0[4] = {ra0.x, ra0.y, ra0.z, ra0.w};
            const float av1[4] = {ra1.x, ra1.y, ra1.z, ra1.w};
            const float bv0[4] = {rb0.x, rb0.y, rb0.z, rb0.w};
            const float bv1[4] = {rb1.x, rb1.y, rb1.z, rb1.w};
#pragma unroll
            for (int j = 0; j < 4; j++) {
                As[nxt][lc + j][lr]      = av0[j];
                As[nxt][lc + j][lr + 64] = av1[j];
                Bs[nxt][lc + j][lr]      = bv0[j];
                Bs[nxt][lc + j][lr + 64] = bv1[j];
            }
            __syncthreads();
        }
    }

    // epilogue: bias (+ReLU) fused, float4 stores
    const float4 bi0 = *(const float4*)(bias + bn + tx * 4);
    const float4 bi1 = *(const float4*)(bias + bn + tx * 4 + 64);
    const float bic[8] = {bi0.x, bi0.y, bi0.z, bi0.w, bi1.x, bi1.y, bi1.z, bi1.w};
#pragma unroll
    for (int i = 0; i < 8; i++) {
        const int row = bm + ty * 4 + ((i < 4) ? i : (60 + i));  // i>=4 -> +64+(i-4)
        float4 c0, c1;
        float v;
        v = acc[i][0] + bic[0]; c0.x = RELU ? fmaxf(v, 0.f) : v;
        v = acc[i][1] + bic[1]; c0.y = RELU ? fmaxf(v, 0.f) : v;
        v = acc[i][2] + bic[2]; c0.z = RELU ? fmaxf(v, 0.f) : v;
        v = acc[i][3] + bic[3]; c0.w = RELU ? fmaxf(v, 0.f) : v;
        v = acc[i][4] + bic[4]; c1.x = RELU ? fmaxf(v, 0.f) : v;
        v = acc[i][5] + bic[5]; c1.y = RELU ? fmaxf(v, 0.f) : v;
        v = acc[i][6] + bic[6]; c1.z = RELU ? fmaxf(v, 0.f) : v;
        v = acc[i][7] + bic[7]; c1.w = RELU ? fmaxf(v, 0.f) : v;
        *(float4*)(C + (size_t)row * N + bn + tx * 4)      = c0;
        *(float4*)(C + (size_t)row * N + bn + tx * 4 + 64) = c1;
    }
}

// ---------------------------------------------------------------------------
// Attention: one block per (b,h); thread = query row. K,V tiles in smem.
// ---------------------------------------------------------------------------
__global__ __launch_bounds__(128)
void attn_kernel(const float* __restrict__ qkv,
                 const int* __restrict__ lens,
                 float* __restrict__ out) {
    const int bh = blockIdx.x;
    const int b  = bh / H_;
    const int h  = bh % H_;
    extern __shared__ float sm[];
    float* Ks = sm;                // [128][64]
    float* Vs = sm + S_ * HD_;     // [128][64]

    for (int i = threadIdx.x; i < S_ * HD_; i += blockDim.x) {
        const int s = i >> 6, d = i & 63;
        const size_t base = (size_t)(b * S_ + s) * (3 * E_) + h * HD_;
        Ks[i] = qkv[base + E_     + d];
        Vs[i] = qkv[base + 2 * E_ + d];
    }
    __syncthreads();

    const int q   = threadIdx.x;
    const int len = lens[b];

    float4 qr[16];
    {
        const float4* qp = (const float4*)(qkv + (size_t)(b * S_ + q) * (3 * E_) + h * HD_);
#pragma unroll
        for (int d = 0; d < 16; d++) qr[d] = qp[d];
    }

    float sc[S_];
    float mx = -3.0e38f;
    for (int k = 0; k < S_; k++) {
        const float4* kp = (const float4*)(Ks + k * HD_);
        float s_ = 0.f;
#pragma unroll
        for (int d = 0; d < 16; d++) {
            float4 kk = kp[d];
            s_ += qr[d].x * kk.x + qr[d].y * kk.y + qr[d].z * kk.z + qr[d].w * kk.w;
        }
        s_ *= 0.125f;
        if (k >= len) s_ -= 1e9f;
        sc[k] = s_;
        mx = fmaxf(mx, s_);
    }
    float sum = 0.f;
    for (int k = 0; k < S_; k++) {
        float e = expf(sc[k] - mx);
        sc[k] = e;
        sum += e;
    }
    const float inv = 1.f / sum;

    float4 acc[16];
#pragma unroll
    for (int d = 0; d < 16; d++) acc[d] = make_float4(0.f, 0.f, 0.f, 0.f);
    for (int k = 0; k < S_; k++) {
        const float p = sc[k] * inv;
        const float4* vp = (const float4*)(Vs + k * HD_);
#pragma unroll
        for (int d = 0; d < 16; d++) {
            float4 vv = vp[d];
            acc[d].x += p * vv.x; acc[d].y += p * vv.y;
            acc[d].z += p * vv.z; acc[d].w += p * vv.w;
        }
    }
    float4* op = (float4*)(out + (size_t)(b * S_ + q) * E_ + h * HD_);
#pragma unroll
    for (int d = 0; d < 16; d++) op[d] = acc[d];
}

// ---------------------------------------------------------------------------
// Fused residual add + LayerNorm
// ---------------------------------------------------------------------------
__global__ __launch_bounds__(256)
void add_ln_kernel(const float* __restrict__ x, const float* __restrict__ y,
                   const float* __restrict__ sc, const float* __restrict__ bi,
                   float* __restrict__ out) {
    const int t = blockIdx.x;
    const int e = threadIdx.x;
    const size_t idx = (size_t)t * E_ + e;
    float v = x[idx] + y[idx];

    __shared__ float red[E_];
    __shared__ float stat;
    red[e] = v;
    __syncthreads();
    for (int o = 128; o; o >>= 1) { if (e < o) red[e] += red[e + o]; __syncthreads(); }
    if (e == 0) stat = red[0] * (1.f / E_);
    __syncthreads();
    const float m = stat;
    const float d = v - m;
    __syncthreads();
    red[e] = d * d;
    __syncthreads();
    for (int o = 128; o; o >>= 1) { if (e < o) red[e] += red[e + o]; __syncthreads(); }
    if (e == 0) stat = red[0] * (1.f / E_);
    __syncthreads();
    out[idx] = d * rsqrtf(stat + 1e-5f) * sc[e] + bi[e];
}

// ---------------------------------------------------------------------------
// Per-sample sigmoid gate
// ---------------------------------------------------------------------------
__global__ void wu_kernel(const float* __restrict__ feat,
                          const float* __restrict__ W,
                          const float* __restrict__ bias,
                          float* __restrict__ wu) {
    const int b = blockIdx.x * blockDim.x + threadIdx.x;
    if (b < B_) {
        float z = bias[0];
#pragma unroll
        for (int i = 0; i < 13; i++) z += feat[b * 13 + i] * W[i];
        wu[b] = 1.f / (1.f + expf(-z));
    }
}

// ---------------------------------------------------------------------------
// Weighted pool + concat
// ---------------------------------------------------------------------------
__global__ __launch_bounds__(256)
void pool_kernel(const float* __restrict__ x, const float* __restrict__ attr_tf,
                 const int* __restrict__ lens, const int* __restrict__ lens_user,
                 const float* __restrict__ wu,
                 const int* __restrict__ user_ids, const int* __restrict__ item_ids,
                 const float* __restrict__ user_emb, const float* __restrict__ item_emb,
                 float* __restrict__ out) {
    const int b = blockIdx.x;
    const int e = threadIdx.x;
    __shared__ float w[S_];
    if (e < S_) {
        const int s = e;
        float wgt = 0.f;
        if (s < lens[b]) {
            const float g = (s < lens_user[b]) ? wu[b] : (1.f - wu[b]);
            wgt = attr_tf[b * S_ + s] * g;
        }
        w[s] = wgt;
    }
    __syncthreads();
    float acc = 0.f;
    const float* xb = x + (size_t)b * S_ * E_ + e;
    for (int s = 0; s < S_; s++) acc += w[s] * xb[(size_t)s * E_];
    out[(size_t)b * 3 * E_ + E_ + e]     = acc;
    out[(size_t)b * 3 * E_ + e]          = user_emb[(size_t)user_ids[b] * E_ + e];
    out[(size_t)b * 3 * E_ + 2 * E_ + e] = item_emb[(size_t)item_ids[b] * E_ + e];
}

// ---------------------------------------------------------------------------
// Scoring head: one warp per (b, target)
// ---------------------------------------------------------------------------
__global__ __launch_bounds__(256)
void logits_kernel(const float* __restrict__ outv, const float* __restrict__ out_emb,
                   const int* __restrict__ pos_t, const int* __restrict__ pos_l,
                   const int* __restrict__ neg_t, const int* __restrict__ neg_l,
                   float* __restrict__ dout) {
    const int gw   = (int)((blockIdx.x * blockDim.x + threadIdx.x) >> 5);
    const int lane = threadIdx.x & 31;
    if (gw >= B_ * NT_) return;
    const int b = gw / NT_;
    const int j = gw % NT_;
    int tgt; float valid, is_pos;
    if (j < P_) {
        tgt = pos_t[b * P_ + j];
        valid = (j < pos_l[b]) ? 1.f : 0.f;
        is_pos = 1.f;
    } else {
        const int jn = j - P_;
        tgt = neg_t[b * N_ + jn];
        valid = (jn < neg_l[b]) ? 1.f : 0.f;
        is_pos = 0.f;
    }
    const float* er = out_emb + (size_t)tgt * (3 * E_);
    const float* ov = outv + (size_t)b * (3 * E_);
    float acc = 0.f;
    for (int k = lane; k < 3 * E_; k += 32) acc += er[k] * ov[k];
#pragma unroll
    for (int o = 16; o; o >>= 1) acc += __shfl_xor_sync(0xffffffffu, acc, o);
    if (lane == 0) {
        const int idx = b * NT_ + j;
        dout[idx]                 = acc;
        dout[B_ * NT_ + idx]      = valid;
        dout[2 * B_ * NT_ + idx]  = is_pos * valid;
    }
}

// ---------------------------------------------------------------------------
// Launch
// ---------------------------------------------------------------------------
extern "C" void kernel_launch(void* const* d_in, const int* in_sizes, int n_in,
                              void* d_out, int out_size) {
    const int*   attr           = (const int*)  d_in[0];
    const float* attr_tf        = (const float*)d_in[2];
    const float* attr_feat      = (const float*)d_in[3];
    const int*   attr_lens      = (const int*)  d_in[4];
    const int*   attr_lens_user = (const int*)  d_in[5];
    const int*   user_ids       = (const int*)  d_in[7];
    const int*   item_ids       = (const int*)  d_in[8];
    const int*   pos_targets    = (const int*)  d_in[9];
    const int*   pos_lens       = (const int*)  d_in[10];
    const int*   neg_targets    = (const int*)  d_in[11];
    const int*   neg_lens       = (const int*)  d_in[12];
    const float* attr_emb       = (const float*)d_in[13];
    const float* user_emb       = (const float*)d_in[14];
    const float* item_emb       = (const float*)d_in[15];
    const float* out_emb        = (const float*)d_in[16];
    const float* fw_W           = (const float*)d_in[17];
    const float* fw_b           = (const float*)d_in[18];
    const float* qkv_w          = (const float*)d_in[19];
    const float* qkv_b          = (const float*)d_in[20];
    const float* attn_out_w     = (const float*)d_in[21];
    const float* attn_out_b     = (const float*)d_in[22];
    const float* ln1_s          = (const float*)d_in[23];
    const float* ln1_b          = (const float*)d_in[24];
    const float* ff1_w          = (const float*)d_in[25];
    const float* ff1_b          = (const float*)d_in[26];
    const float* ff2_w          = (const float*)d_in[27];
    const float* ff2_b          = (const float*)d_in[28];
    const float* ln2_s          = (const float*)d_in[29];
    const float* ln2_b          = (const float*)d_in[30];

    float *x, *qkv, *attn, *tmp, *ff, *outv, *wu;
    cudaGetSymbolAddress((void**)&x,    g_x);
    cudaGetSymbolAddress((void**)&qkv,  g_qkv);
    cudaGetSymbolAddress((void**)&attn, g_attn);
    cudaGetSymbolAddress((void**)&tmp,  g_tmp);
    cudaGetSymbolAddress((void**)&ff,   g_ff);
    cudaGetSymbolAddress((void**)&outv, g_out);
    cudaGetSymbolAddress((void**)&wu,   g_wu);

    const int attn_smem = 2 * S_ * HD_ * (int)sizeof(float);  // 64 KB
    cudaFuncSetAttribute(attn_kernel, cudaFuncAttributeMaxDynamicSharedMemorySize,
                         attn_smem);

    gather_kernel<<<T_, 256>>>(attr, attr_emb, x);

    for (int l = 0; l < L_; l++) {
        const float* lqkv_w = qkv_w      + (size_t)l * 3 * E_ * E_;
        const float* lqkv_b = qkv_b      + (size_t)l * 3 * E_;
        const float* lao_w  = attn_out_w + (size_t)l * E_ * E_;
        const float* lao_b  = attn_out_b + (size_t)l * E_;
        const float* l1s    = ln1_s + (size_t)l * E_;
        const float* l1b    = ln1_b + (size_t)l * E_;
        const float* lf1_w  = ff1_w + (size_t)l * F_ * E_;
        const float* lf1_b  = ff1_b + (size_t)l * F_;
        const float* lf2_w  = ff2_w + (size_t)l * E_ * F_;
        const float* lf2_b  = ff2_b + (size_t)l * E_;
        const float* l2s    = ln2_s + (size_t)l * E_;
        const float* l2b    = ln2_b + (size_t)l * E_;

        // QKV: [32768,768] = x @ Wqkv^T
        sgemm128<false><<<dim3(3 * E_ / 128, T_ / 128), 256>>>(
            x, lqkv_w, lqkv_b, qkv, T_, 3 * E_, E_);
        attn_kernel<<<B_ * H_, S_, attn_smem>>>(qkv, attr_lens, attn);
        // proj
        sgemm128<false><<<dim3(E_ / 128, T_ / 128), 256>>>(
            attn, lao_w, lao_b, tmp, T_, E_, E_);
        add_ln_kernel<<<T_, E_>>>(x, tmp, l1s, l1b, x);
        // FF1 (+ReLU)
        sgemm128<true><<<dim3(F_ / 128, T_ / 128), 256>>>(
            x, lf1_w, lf1_b, ff, T_, F_, E_);
        // FF2
        sgemm128<false><<<dim3(E_ / 128, T_ / 128), 256>>>(
            ff, lf2_w, lf2_b, tmp, T_, E_, F_);
        add_ln_kernel<<<T_, E_>>>(x, tmp, l2s, l2b, x);
    }

    wu_kernel<<<1, 256>>>(attr_feat, fw_W, fw_b, wu);
    pool_kernel<<<B_, 256>>>(x, attr_tf, attr_lens, attr_lens_user, wu,
                             user_ids, item_ids, user_emb, item_emb, outv);

    const int nwarps = B_ * NT_;
    logits_kernel<<<(nwarps * 32 + 255) / 256, 256>>>(
        outv, out_emb, pos_targets, pos_lens, neg_targets, neg_lens,
        (float*)d_out);
}

// round 3
// speedup vs baseline: 2.2236x; 1.4267x over previous
#include <cuda_runtime.h>
#include <cuda_bf16.h>
#include <math.h>
#include <stdint.h>

// Problem constants
#define B_   256
#define S_   128
#define P_   100
#define N_   500
#define E_   256
#define H_   4
#define HD_  64
#define L_   2
#define F_   1024
#define T_   (B_ * S_)      // 32768 tokens
#define NT_  (P_ + N_)      // 600 targets

// ---------------------------------------------------------------------------
// Scratch (device globals — no allocation allowed)
// ---------------------------------------------------------------------------
__device__ float g_x   [(size_t)T_ * E_];
__device__ float g_qkv [(size_t)T_ * 3 * E_];
__device__ float g_attn[(size_t)T_ * E_];
__device__ float g_tmp [(size_t)T_ * E_];
__device__ float g_ff  [(size_t)T_ * F_];
__device__ float g_out [(size_t)B_ * 3 * E_];
__device__ float g_wu  [B_];

// ---------------------------------------------------------------------------
// Embedding gather
// ---------------------------------------------------------------------------
__global__ void gather_kernel(const int* __restrict__ attr,
                              const float* __restrict__ emb,
                              float* __restrict__ x) {
    size_t i = (size_t)blockIdx.x * blockDim.x + threadIdx.x;
    if (i < (size_t)T_ * E_) {
        int t = (int)(i >> 8);
        int e = (int)(i & (E_ - 1));
        x[i] = emb[(size_t)attr[t] * E_ + e];
    }
}

// ---------------------------------------------------------------------------
// TF32 tensor-core GEMM: C[M,N] = A[M,K] @ B[N,K]^T + bias[N] (opt ReLU)
// 128x128 block tile, BK=16, 256 threads (8 warps), warp tile 64x32
// (4x4 grid of m16n8k8 fragments). Smem rows stride 20 -> fragment loads
// hit all 32 banks (bank = 4*m + k, m in 0..7, k in 0..3). Double buffered.
// Inputs rounded to tf32 via cvt.rna during smem store; fp32 accumulate.
// Requires M%128==0, N%128==0, K%16==0.
// ---------------------------------------------------------------------------
#define LDA 20

__device__ __forceinline__ uint32_t f2tf32(float x) {
    uint32_t r;
    asm("cvt.rna.tf32.f32 %0, %1;" : "=r"(r) : "f"(x));
    return r;
}

__device__ __forceinline__ void mma_tf32(float* d, const uint32_t* a, const uint32_t* b) {
    asm volatile(
        "mma.sync.aligned.m16n8k8.row.col.f32.tf32.tf32.f32 "
        "{%0,%1,%2,%3}, {%4,%5,%6,%7}, {%8,%9}, {%0,%1,%2,%3};"
        : "+f"(d[0]), "+f"(d[1]), "+f"(d[2]), "+f"(d[3])
        : "r"(a[0]), "r"(a[1]), "r"(a[2]), "r"(a[3]), "r"(b[0]), "r"(b[1]));
}

template<bool RELU>
__global__ __launch_bounds__(256)
void tgemm(const float* __restrict__ A, const float* __restrict__ Bm,
           const float* __restrict__ bias, float* __restrict__ C,
           int M, int N, int K) {
    __shared__ uint32_t As[2][128][LDA];
    __shared__ uint32_t Bs[2][128][LDA];

    const int bm   = blockIdx.y * 128;
    const int bn   = blockIdx.x * 128;
    const int t    = threadIdx.x;
    const int lane = t & 31;
    const int wid  = t >> 5;
    const int wm   = (wid & 1) * 64;   // warp m offset
    const int wn   = (wid >> 1) * 32;  // warp n offset
    const int g    = lane >> 2;        // group id 0..7
    const int tg   = lane & 3;         // thread-in-group 0..3

    // staging load indices: 128 rows x 16 k per matrix, 2 float4 per thread
    const int lm = t >> 2;            // 0..63
    const int lk = (t & 3) * 4;       // 0,4,8,12

    const float* Ap0 = A  + (size_t)(bm + lm)      * K + lk;
    const float* Ap1 = A  + (size_t)(bm + lm + 64) * K + lk;
    const float* Bp0 = Bm + (size_t)(bn + lm)      * K + lk;
    const float* Bp1 = Bm + (size_t)(bn + lm + 64) * K + lk;

    float acc[4][4][4];
#pragma unroll
    for (int i = 0; i < 4; i++)
#pragma unroll
        for (int j = 0; j < 4; j++)
#pragma unroll
            for (int r = 0; r < 4; r++) acc[i][j][r] = 0.f;

    float4 ra0, ra1, rb0, rb1;

    // prologue: fill stage 0
    ra0 = *(const float4*)Ap0; ra1 = *(const float4*)Ap1;
    rb0 = *(const float4*)Bp0; rb1 = *(const float4*)Bp1;
    {
        const float a0v[4] = {ra0.x, ra0.y, ra0.z, ra0.w};
        const float a1v[4] = {ra1.x, ra1.y, ra1.z, ra1.w};
        const float b0v[4] = {rb0.x, rb0.y, rb0.z, rb0.w};
        const float b1v[4] = {rb1.x, rb1.y, rb1.z, rb1.w};
#pragma unroll
        for (int j = 0; j < 4; j++) {
            As[0][lm][lk + j]      = f2tf32(a0v[j]);
            As[0][lm + 64][lk + j] = f2tf32(a1v[j]);
            Bs[0][lm][lk + j]      = f2tf32(b0v[j]);
            Bs[0][lm + 64][lk + j] = f2tf32(b1v[j]);
        }
    }
    __syncthreads();

    const int nk = K >> 4;
    for (int kt = 0; kt < nk; kt++) {
        const int cur = kt & 1;
        const bool more = (kt + 1 < nk);
        if (more) {
            const int k0 = (kt + 1) << 4;
            ra0 = *(const float4*)(Ap0 + k0); ra1 = *(const float4*)(Ap1 + k0);
            rb0 = *(const float4*)(Bp0 + k0); rb1 = *(const float4*)(Bp1 + k0);
        }
#pragma unroll
        for (int ks = 0; ks < 2; ks++) {
            const int k0 = ks * 8;
            uint32_t af[4][4], bf[4][2];
#pragma unroll
            for (int mf = 0; mf < 4; mf++) {
                const int row = wm + mf * 16 + g;
                af[mf][0] = As[cur][row][k0 + tg];
                af[mf][1] = As[cur][row + 8][k0 + tg];
                af[mf][2] = As[cur][row][k0 + tg + 4];
                af[mf][3] = As[cur][row + 8][k0 + tg + 4];
            }
#pragma unroll
            for (int nf = 0; nf < 4; nf++) {
                const int col = wn + nf * 8 + g;
                bf[nf][0] = Bs[cur][col][k0 + tg];
                bf[nf][1] = Bs[cur][col][k0 + tg + 4];
            }
#pragma unroll
            for (int mf = 0; mf < 4; mf++)
#pragma unroll
                for (int nf = 0; nf < 4; nf++)
                    mma_tf32(acc[mf][nf], af[mf], bf[nf]);
        }
        if (more) {
            __syncthreads();
            const int nxt = cur ^ 1;
            const float a0v[4] = {ra0.x, ra0.y, ra0.z, ra0.w};
            const float a1v[4] = {ra1.x, ra1.y, ra1.z, ra1.w};
            const float b0v[4] = {rb0.x, rb0.y, rb0.z, rb0.w};
            const float b1v[4] = {rb1.x, rb1.y, rb1.z, rb1.w};
#pragma unroll
            for (int j = 0; j < 4; j++) {
                As[nxt][lm][lk + j]      = f2tf32(a0v[j]);
                As[nxt][lm + 64][lk + j] = f2tf32(a1v[j]);
                Bs[nxt][lm][lk + j]      = f2tf32(b0v[j]);
                Bs[nxt][lm + 64][lk + j] = f2tf32(b1v[j]);
            }
            __syncthreads();
        }
    }

    // epilogue: bias (+ReLU), float2 stores
#pragma unroll
    for (int mf = 0; mf < 4; mf++) {
        const int row = bm + wm + mf * 16 + g;
#pragma unroll
        for (int nf = 0; nf < 4; nf++) {
            const int col = bn + wn + nf * 8 + 2 * tg;
            const float b0v = bias[col], b1v = bias[col + 1];
            float v0 = acc[mf][nf][0] + b0v;
            float v1 = acc[mf][nf][1] + b1v;
            float v2 = acc[mf][nf][2] + b0v;
            float v3 = acc[mf][nf][3] + b1v;
            if (RELU) {
                v0 = fmaxf(v0, 0.f); v1 = fmaxf(v1, 0.f);
                v2 = fmaxf(v2, 0.f); v3 = fmaxf(v3, 0.f);
            }
            *(float2*)(C + (size_t)row * N + col)       = make_float2(v0, v1);
            *(float2*)(C + (size_t)(row + 8) * N + col) = make_float2(v2, v3);
        }
    }
}

// ---------------------------------------------------------------------------
// Attention: one block per (b,h); thread = query row. K,V tiles in smem.
// ---------------------------------------------------------------------------
__global__ __launch_bounds__(128)
void attn_kernel(const float* __restrict__ qkv,
                 const int* __restrict__ lens,
                 float* __restrict__ out) {
    const int bh = blockIdx.x;
    const int b  = bh / H_;
    const int h  = bh % H_;
    extern __shared__ float sm[];
    float* Ks = sm;
    float* Vs = sm + S_ * HD_;

    for (int i = threadIdx.x; i < S_ * HD_; i += blockDim.x) {
        const int s = i >> 6, d = i & 63;
        const size_t base = (size_t)(b * S_ + s) * (3 * E_) + h * HD_;
        Ks[i] = qkv[base + E_     + d];
        Vs[i] = qkv[base + 2 * E_ + d];
    }
    __syncthreads();

    const int q   = threadIdx.x;
    const int len = lens[b];

    float4 qr[16];
    {
        const float4* qp = (const float4*)(qkv + (size_t)(b * S_ + q) * (3 * E_) + h * HD_);
#pragma unroll
        for (int d = 0; d < 16; d++) qr[d] = qp[d];
    }

    float sc[S_];
    float mx = -3.0e38f;
    for (int k = 0; k < S_; k++) {
        const float4* kp = (const float4*)(Ks + k * HD_);
        float s_ = 0.f;
#pragma unroll
        for (int d = 0; d < 16; d++) {
            float4 kk = kp[d];
            s_ += qr[d].x * kk.x + qr[d].y * kk.y + qr[d].z * kk.z + qr[d].w * kk.w;
        }
        s_ *= 0.125f;
        if (k >= len) s_ -= 1e9f;
        sc[k] = s_;
        mx = fmaxf(mx, s_);
    }
    float sum = 0.f;
    for (int k = 0; k < S_; k++) {
        float e = expf(sc[k] - mx);
        sc[k] = e;
        sum += e;
    }
    const float inv = 1.f / sum;

    float4 acc[16];
#pragma unroll
    for (int d = 0; d < 16; d++) acc[d] = make_float4(0.f, 0.f, 0.f, 0.f);
    for (int k = 0; k < S_; k++) {
        const float p = sc[k] * inv;
        const float4* vp = (const float4*)(Vs + k * HD_);
#pragma unroll
        for (int d = 0; d < 16; d++) {
            float4 vv = vp[d];
            acc[d].x += p * vv.x; acc[d].y += p * vv.y;
            acc[d].z += p * vv.z; acc[d].w += p * vv.w;
        }
    }
    float4* op = (float4*)(out + (size_t)(b * S_ + q) * E_ + h * HD_);
#pragma unroll
    for (int d = 0; d < 16; d++) op[d] = acc[d];
}

// ---------------------------------------------------------------------------
// Fused residual add + LayerNorm
// ---------------------------------------------------------------------------
__global__ __launch_bounds__(256)
void add_ln_kernel(const float* __restrict__ x, const float* __restrict__ y,
                   const float* __restrict__ sc, const float* __restrict__ bi,
                   float* __restrict__ out) {
    const int t = blockIdx.x;
    const int e = threadIdx.x;
    const size_t idx = (size_t)t * E_ + e;
    float v = x[idx] + y[idx];

    __shared__ float red[E_];
    __shared__ float stat;
    red[e] = v;
    __syncthreads();
    for (int o = 128; o; o >>= 1) { if (e < o) red[e] += red[e + o]; __syncthreads(); }
    if (e == 0) stat = red[0] * (1.f / E_);
    __syncthreads();
    const float m = stat;
    const float d = v - m;
    __syncthreads();
    red[e] = d * d;
    __syncthreads();
    for (int o = 128; o; o >>= 1) { if (e < o) red[e] += red[e + o]; __syncthreads(); }
    if (e == 0) stat = red[0] * (1.f / E_);
    __syncthreads();
    out[idx] = d * rsqrtf(stat + 1e-5f) * sc[e] + bi[e];
}

// ---------------------------------------------------------------------------
// Per-sample sigmoid gate
// ---------------------------------------------------------------------------
__global__ void wu_kernel(const float* __restrict__ feat,
                          const float* __restrict__ W,
                          const float* __restrict__ bias,
                          float* __restrict__ wu) {
    const int b = blockIdx.x * blockDim.x + threadIdx.x;
    if (b < B_) {
        float z = bias[0];
#pragma unroll
        for (int i = 0; i < 13; i++) z += feat[b * 13 + i] * W[i];
        wu[b] = 1.f / (1.f + expf(-z));
    }
}

// ---------------------------------------------------------------------------
// Weighted pool + concat
// ---------------------------------------------------------------------------
__global__ __launch_bounds__(256)
void pool_kernel(const float* __restrict__ x, const float* __restrict__ attr_tf,
                 const int* __restrict__ lens, const int* __restrict__ lens_user,
                 const float* __restrict__ wu,
                 const int* __restrict__ user_ids, const int* __restrict__ item_ids,
                 const float* __restrict__ user_emb, const float* __restrict__ item_emb,
                 float* __restrict__ out) {
    const int b = blockIdx.x;
    const int e = threadIdx.x;
    __shared__ float w[S_];
    if (e < S_) {
        const int s = e;
        float wgt = 0.f;
        if (s < lens[b]) {
            const float g = (s < lens_user[b]) ? wu[b] : (1.f - wu[b]);
            wgt = attr_tf[b * S_ + s] * g;
        }
        w[s] = wgt;
    }
    __syncthreads();
    float acc = 0.f;
    const float* xb = x + (size_t)b * S_ * E_ + e;
    for (int s = 0; s < S_; s++) acc += w[s] * xb[(size_t)s * E_];
    out[(size_t)b * 3 * E_ + E_ + e]     = acc;
    out[(size_t)b * 3 * E_ + e]          = user_emb[(size_t)user_ids[b] * E_ + e];
    out[(size_t)b * 3 * E_ + 2 * E_ + e] = item_emb[(size_t)item_ids[b] * E_ + e];
}

// ---------------------------------------------------------------------------
// Scoring head: one warp per (b, target)
// ---------------------------------------------------------------------------
__global__ __launch_bounds__(256)
void logits_kernel(const float* __restrict__ outv, const float* __restrict__ out_emb,
                   const int* __restrict__ pos_t, const int* __restrict__ pos_l,
                   const int* __restrict__ neg_t, const int* __restrict__ neg_l,
                   float* __restrict__ dout) {
    const int gw   = (int)((blockIdx.x * blockDim.x + threadIdx.x) >> 5);
    const int lane = threadIdx.x & 31;
    if (gw >= B_ * NT_) return;
    const int b = gw / NT_;
    const int j = gw % NT_;
    int tgt; float valid, is_pos;
    if (j < P_) {
        tgt = pos_t[b * P_ + j];
        valid = (j < pos_l[b]) ? 1.f : 0.f;
        is_pos = 1.f;
    } else {
        const int jn = j - P_;
        tgt = neg_t[b * N_ + jn];
        valid = (jn < neg_l[b]) ? 1.f : 0.f;
        is_pos = 0.f;
    }
    const float* er = out_emb + (size_t)tgt * (3 * E_);
    const float* ov = outv + (size_t)b * (3 * E_);
    float acc = 0.f;
    for (int k = lane; k < 3 * E_; k += 32) acc += er[k] * ov[k];
#pragma unroll
    for (int o = 16; o; o >>= 1) acc += __shfl_xor_sync(0xffffffffu, acc, o);
    if (lane == 0) {
        const int idx = b * NT_ + j;
        dout[idx]                 = acc;
        dout[B_ * NT_ + idx]      = valid;
        dout[2 * B_ * NT_ + idx]  = is_pos * valid;
    }
}

// ---------------------------------------------------------------------------
// Launch
// ---------------------------------------------------------------------------
extern "C" void kernel_launch(void* const* d_in, const int* in_sizes, int n_in,
                              void* d_out, int out_size) {
    const int*   attr           = (const int*)  d_in[0];
    const float* attr_tf        = (const float*)d_in[2];
    const float* attr_feat      = (const float*)d_in[3];
    const int*   attr_lens      = (const int*)  d_in[4];
    const int*   attr_lens_user = (const int*)  d_in[5];
    const int*   user_ids       = (const int*)  d_in[7];
    const int*   item_ids       = (const int*)  d_in[8];
    const int*   pos_targets    = (const int*)  d_in[9];
    const int*   pos_lens       = (const int*)  d_in[10];
    const int*   neg_targets    = (const int*)  d_in[11];
    const int*   neg_lens       = (const int*)  d_in[12];
    const float* attr_emb       = (const float*)d_in[13];
    const float* user_emb       = (const float*)d_in[14];
    const float* item_emb       = (const float*)d_in[15];
    const float* out_emb        = (const float*)d_in[16];
    const float* fw_W           = (const float*)d_in[17];
    const float* fw_b           = (const float*)d_in[18];
    const float* qkv_w          = (const float*)d_in[19];
    const float* qkv_b          = (const float*)d_in[20];
    const float* attn_out_w     = (const float*)d_in[21];
    const float* attn_out_b     = (const float*)d_in[22];
    const float* ln1_s          = (const float*)d_in[23];
    const float* ln1_b          = (const float*)d_in[24];
    const float* ff1_w          = (const float*)d_in[25];
    const float* ff1_b          = (const float*)d_in[26];
    const float* ff2_w          = (const float*)d_in[27];
    const float* ff2_b          = (const float*)d_in[28];
    const float* ln2_s          = (const float*)d_in[29];
    const float* ln2_b          = (const float*)d_in[30];

    float *x, *qkv, *attn, *tmp, *ff, *outv, *wu;
    cudaGetSymbolAddress((void**)&x,    g_x);
    cudaGetSymbolAddress((void**)&qkv,  g_qkv);
    cudaGetSymbolAddress((void**)&attn, g_attn);
    cudaGetSymbolAddress((void**)&tmp,  g_tmp);
    cudaGetSymbolAddress((void**)&ff,   g_ff);
    cudaGetSymbolAddress((void**)&outv, g_out);
    cudaGetSymbolAddress((void**)&wu,   g_wu);

    const int attn_smem = 2 * S_ * HD_ * (int)sizeof(float);  // 64 KB
    cudaFuncSetAttribute(attn_kernel, cudaFuncAttributeMaxDynamicSharedMemorySize,
                         attn_smem);

    gather_kernel<<<T_, 256>>>(attr, attr_emb, x);

    for (int l = 0; l < L_; l++) {
        const float* lqkv_w = qkv_w      + (size_t)l * 3 * E_ * E_;
        const float* lqkv_b = qkv_b      + (size_t)l * 3 * E_;
        const float* lao_w  = attn_out_w + (size_t)l * E_ * E_;
        const float* lao_b  = attn_out_b + (size_t)l * E_;
        const float* l1s    = ln1_s + (size_t)l * E_;
        const float* l1b    = ln1_b + (size_t)l * E_;
        const float* lf1_w  = ff1_w + (size_t)l * F_ * E_;
        const float* lf1_b  = ff1_b + (size_t)l * F_;
        const float* lf2_w  = ff2_w + (size_t)l * E_ * F_;
        const float* lf2_b  = ff2_b + (size_t)l * E_;
        const float* l2s    = ln2_s + (size_t)l * E_;
        const float* l2b    = ln2_b + (size_t)l * E_;

        tgemm<false><<<dim3(3 * E_ / 128, T_ / 128), 256>>>(
            x, lqkv_w, lqkv_b, qkv, T_, 3 * E_, E_);
        attn_kernel<<<B_ * H_, S_, attn_smem>>>(qkv, attr_lens, attn);
        tgemm<false><<<dim3(E_ / 128, T_ / 128), 256>>>(
            attn, lao_w, lao_b, tmp, T_, E_, E_);
        add_ln_kernel<<<T_, E_>>>(x, tmp, l1s, l1b, x);
        tgemm<true><<<dim3(F_ / 128, T_ / 128), 256>>>(
            x, lf1_w, lf1_b, ff, T_, F_, E_);
        tgemm<false><<<dim3(E_ / 128, T_ / 128), 256>>>(
            ff, lf2_w, lf2_b, tmp, T_, E_, F_);
        add_ln_kernel<<<T_, E_>>>(x, tmp, l2s, l2b, x);
    }

    wu_kernel<<<1, 256>>>(attr_feat, fw_W, fw_b, wu);
    pool_kernel<<<B_, 256>>>(x, attr_tf, attr_lens, attr_lens_user, wu,
                             user_ids, item_ids, user_emb, item_emb, outv);

    const int nwarps = B_ * NT_;
    logits_kernel<<<(nwarps * 32 + 255) / 256, 256>>>(
        outv, out_emb, pos_targets, pos_lens, neg_targets, neg_lens,
        (float*)d_out);
}

// round 4
// speedup vs baseline: 2.8062x; 1.2620x over previous
#include <cuda_runtime.h>
#include <cuda_bf16.h>
#include <math.h>
#include <stdint.h>

// Problem constants
#define B_   256
#define S_   128
#define P_   100
#define N_   500
#define E_   256
#define H_   4
#define HD_  64
#define L_   2
#define F_   1024
#define T_   (B_ * S_)      // 32768 tokens
#define NT_  (P_ + N_)      // 600 targets

// ---------------------------------------------------------------------------
// Scratch (device globals — no allocation allowed)
// ---------------------------------------------------------------------------
__device__ float g_x   [(size_t)T_ * E_];
__device__ float g_qkv [(size_t)T_ * 3 * E_];
__device__ float g_attn[(size_t)T_ * E_];
__device__ float g_tmp [(size_t)T_ * E_];
__device__ float g_ff  [(size_t)T_ * F_];
__device__ float g_out [(size_t)B_ * 3 * E_];
__device__ float g_wu  [B_];

// ---------------------------------------------------------------------------
// cp.async helpers
// ---------------------------------------------------------------------------
__device__ __forceinline__ void cp16(void* sdst, const void* gsrc) {
    uint32_t s = (uint32_t)__cvta_generic_to_shared(sdst);
    asm volatile("cp.async.cg.shared.global [%0], [%1], 16;\n" :: "r"(s), "l"(gsrc));
}
__device__ __forceinline__ void cp_commit() {
    asm volatile("cp.async.commit_group;\n");
}
template<int NWait>
__device__ __forceinline__ void cp_wait() {
    asm volatile("cp.async.wait_group %0;\n" :: "n"(NWait));
}

// ---------------------------------------------------------------------------
// Embedding gather (float4)
// ---------------------------------------------------------------------------
__global__ void gather_kernel(const int* __restrict__ attr,
                              const float* __restrict__ emb,
                              float* __restrict__ x) {
    int i4 = blockIdx.x * blockDim.x + threadIdx.x;
    if (i4 < T_ * (E_ / 4)) {
        int t = i4 >> 6;
        int e4 = i4 & 63;
        ((float4*)x)[i4] = ((const float4*)emb)[(size_t)attr[t] * (E_ / 4) + e4];
    }
}

// ---------------------------------------------------------------------------
// TF32 tensor-core GEMM: C[M,N] = A[M,K] @ B[N,K]^T + bias[N] (opt ReLU)
// Block tile 128x256, BK=16, 256 threads (8 warps), warp tile 64x64
// (4x8 grid of m16n8k8 fragments). Smem layout [rows][20] (stride-20 words
// -> conflict-free fragment reads). Staging via cp.async.cg 16B, double
// buffered. TF32 via hardware truncation of fp32 operands.
// Requires M%128==0, N%256==0, K%16==0.
// ---------------------------------------------------------------------------
#define LDA 20
#define ASZ (128 * LDA)      // one A stage in words
#define BSZ (256 * LDA)      // one B stage in words

template<bool RELU>
__global__ __launch_bounds__(256)
void tgemm(const float* __restrict__ A, const float* __restrict__ Bm,
           const float* __restrict__ bias, float* __restrict__ C,
           int M, int N, int K) {
    extern __shared__ uint32_t smw[];
    uint32_t* As = smw;                 // [2][128][LDA]
    uint32_t* Bs = smw + 2 * ASZ;       // [2][256][LDA]

    const int bm   = blockIdx.y * 128;
    const int bn   = blockIdx.x * 256;
    const int t    = threadIdx.x;
    const int lane = t & 31;
    const int wid  = t >> 5;
    const int wm   = (wid & 1) * 64;
    const int wn   = (wid >> 1) * 64;
    const int g    = lane >> 2;
    const int tg   = lane & 3;

    // staging: A: row = t>>1 (0..127), k half = (t&1)*8 ; B: col = t, 16 k
    const int arow = t >> 1;
    const int akb  = (t & 1) * 8;
    const float* Ap = A  + (size_t)(bm + arow) * K + akb;
    const float* Bp = Bm + (size_t)(bn + t) * K;

    float acc[4][8][4];
#pragma unroll
    for (int i = 0; i < 4; i++)
#pragma unroll
        for (int j = 0; j < 8; j++)
#pragma unroll
            for (int r = 0; r < 4; r++) acc[i][j][r] = 0.f;

    // prologue: stage 0
    cp16(&As[arow * LDA + akb],     Ap);
    cp16(&As[arow * LDA + akb + 4], Ap + 4);
#pragma unroll
    for (int j = 0; j < 4; j++)
        cp16(&Bs[t * LDA + j * 4], Bp + j * 4);
    cp_commit();

    const int nk = K >> 4;
    for (int kt = 0; kt < nk; kt++) {
        const int cur = kt & 1;
        const bool more = (kt + 1 < nk);
        if (more) {
            const int nxt = cur ^ 1;
            const int k0 = (kt + 1) << 4;
            cp16(&As[nxt * ASZ + arow * LDA + akb],     Ap + k0);
            cp16(&As[nxt * ASZ + arow * LDA + akb + 4], Ap + k0 + 4);
#pragma unroll
            for (int j = 0; j < 4; j++)
                cp16(&Bs[nxt * BSZ + t * LDA + j * 4], Bp + k0 + j * 4);
            cp_commit();
            cp_wait<1>();
        } else {
            cp_wait<0>();
        }
        __syncthreads();

        const uint32_t* Ac = As + cur * ASZ;
        const uint32_t* Bc = Bs + cur * BSZ;
#pragma unroll
        for (int ks = 0; ks < 2; ks++) {
            const int k0 = ks * 8;
            uint32_t af[4][4], bf[8][2];
#pragma unroll
            for (int mf = 0; mf < 4; mf++) {
                const int row = wm + mf * 16 + g;
                af[mf][0] = Ac[row * LDA + k0 + tg];
                af[mf][1] = Ac[(row + 8) * LDA + k0 + tg];
                af[mf][2] = Ac[row * LDA + k0 + tg + 4];
                af[mf][3] = Ac[(row + 8) * LDA + k0 + tg + 4];
            }
#pragma unroll
            for (int nf = 0; nf < 8; nf++) {
                const int col = wn + nf * 8 + g;
                bf[nf][0] = Bc[col * LDA + k0 + tg];
                bf[nf][1] = Bc[col * LDA + k0 + tg + 4];
            }
#pragma unroll
            for (int mf = 0; mf < 4; mf++)
#pragma unroll
                for (int nf = 0; nf < 8; nf++) {
                    float* d = acc[mf][nf];
                    asm volatile(
                        "mma.sync.aligned.m16n8k8.row.col.f32.tf32.tf32.f32 "
                        "{%0,%1,%2,%3}, {%4,%5,%6,%7}, {%8,%9}, {%0,%1,%2,%3};"
                        : "+f"(d[0]), "+f"(d[1]), "+f"(d[2]), "+f"(d[3])
                        : "r"(af[mf][0]), "r"(af[mf][1]), "r"(af[mf][2]),
                          "r"(af[mf][3]), "r"(bf[nf][0]), "r"(bf[nf][1]));
                }
        }
        if (more) __syncthreads();
    }

    // epilogue: bias (+ReLU), float2 stores
#pragma unroll
    for (int nf = 0; nf < 8; nf++) {
        const int col = bn + wn + nf * 8 + 2 * tg;
        const float b0v = bias[col], b1v = bias[col + 1];
#pragma unroll
        for (int mf = 0; mf < 4; mf++) {
            const int row = bm + wm + mf * 16 + g;
            float v0 = acc[mf][nf][0] + b0v;
            float v1 = acc[mf][nf][1] + b1v;
            float v2 = acc[mf][nf][2] + b0v;
            float v3 = acc[mf][nf][3] + b1v;
            if (RELU) {
                v0 = fmaxf(v0, 0.f); v1 = fmaxf(v1, 0.f);
                v2 = fmaxf(v2, 0.f); v3 = fmaxf(v3, 0.f);
            }
            *(float2*)(C + (size_t)row * N + col)       = make_float2(v0, v1);
            *(float2*)(C + (size_t)(row + 8) * N + col) = make_float2(v2, v3);
        }
    }
}

// ---------------------------------------------------------------------------
// Attention v2: one block per (b,h), 128 threads (thread = query row).
// Scores kept in smem P[128][129] (pad -> conflict-free). K/V reads are
// warp-broadcast float4s. No register arrays -> no local-memory spills.
// ---------------------------------------------------------------------------
#define PLD 129

__global__ __launch_bounds__(128)
void attn_kernel(const float* __restrict__ qkv,
                 const int* __restrict__ lens,
                 float* __restrict__ out) {
    const int bh = blockIdx.x;
    const int b  = bh / H_;
    const int h  = bh % H_;
    extern __shared__ float sm[];
    float* Ks = sm;                        // [128][64]
    float* Vs = sm + S_ * HD_;             // [128][64]
    float* Pm = sm + 2 * S_ * HD_;         // [128][129]

    // cooperative K/V load (float4)
    for (int i4 = threadIdx.x; i4 < S_ * HD_ / 4; i4 += blockDim.x) {
        const int s  = i4 >> 4;
        const int d4 = i4 & 15;
        const float4* base =
            (const float4*)(qkv + (size_t)(b * S_ + s) * (3 * E_) + h * HD_);
        ((float4*)Ks)[i4] = base[(E_ / 4) + d4];       // K at +256 floats
        ((float4*)Vs)[i4] = base[(2 * E_ / 4) + d4];   // V at +512 floats
    }
    __syncthreads();

    const int q   = threadIdx.x;
    const int len = lens[b];
    float* Pq = Pm + q * PLD;

    float4 qr[16];
    {
        const float4* qp =
            (const float4*)(qkv + (size_t)(b * S_ + q) * (3 * E_) + h * HD_);
#pragma unroll
        for (int d = 0; d < 16; d++) qr[d] = qp[d];
    }

    // scores -> smem, track max
    float mx = -3.0e38f;
    for (int k = 0; k < S_; k++) {
        const float4* kp = (const float4*)(Ks + k * HD_);
        float s_ = 0.f;
#pragma unroll
        for (int d = 0; d < 16; d++) {
            float4 kk = kp[d];
            s_ += qr[d].x * kk.x + qr[d].y * kk.y + qr[d].z * kk.z + qr[d].w * kk.w;
        }
        s_ *= 0.125f;
        if (k >= len) s_ -= 1e9f;
        Pq[k] = s_;
        mx = fmaxf(mx, s_);
    }
    // exp + sum
    float sum = 0.f;
    for (int k = 0; k < S_; k++) {
        float e = __expf(Pq[k] - mx);
        Pq[k] = e;
        sum += e;
    }
    const float inv = 1.f / sum;

    // AV
    float4 acc[16];
#pragma unroll
    for (int d = 0; d < 16; d++) acc[d] = make_float4(0.f, 0.f, 0.f, 0.f);
    for (int k = 0; k < S_; k++) {
        const float p = Pq[k] * inv;
        const float4* vp = (const float4*)(Vs + k * HD_);
#pragma unroll
        for (int d = 0; d < 16; d++) {
            float4 vv = vp[d];
            acc[d].x += p * vv.x; acc[d].y += p * vv.y;
            acc[d].z += p * vv.z; acc[d].w += p * vv.w;
        }
    }
    float4* op = (float4*)(out + (size_t)(b * S_ + q) * E_ + h * HD_);
#pragma unroll
    for (int d = 0; d < 16; d++) op[d] = acc[d];
}

// ---------------------------------------------------------------------------
// Fused residual add + LayerNorm: warp per token, 8 tokens per block
// ---------------------------------------------------------------------------
__global__ __launch_bounds__(256)
void add_ln_kernel(const float* __restrict__ x, const float* __restrict__ y,
                   const float* __restrict__ sc, const float* __restrict__ bi,
                   float* __restrict__ out) {
    const int tok  = blockIdx.x * 8 + (threadIdx.x >> 5);
    const int lane = threadIdx.x & 31;
    const size_t base4 = (size_t)tok * (E_ / 4);

    float4 v0 = ((const float4*)x)[base4 + lane];
    float4 v1 = ((const float4*)x)[base4 + 32 + lane];
    float4 y0 = ((const float4*)y)[base4 + lane];
    float4 y1 = ((const float4*)y)[base4 + 32 + lane];
    v0.x += y0.x; v0.y += y0.y; v0.z += y0.z; v0.w += y0.w;
    v1.x += y1.x; v1.y += y1.y; v1.z += y1.z; v1.w += y1.w;

    float s = v0.x + v0.y + v0.z + v0.w + v1.x + v1.y + v1.z + v1.w;
#pragma unroll
    for (int o = 16; o; o >>= 1) s += __shfl_xor_sync(0xffffffffu, s, o);
    const float m = s * (1.f / E_);

    float q =
        (v0.x - m) * (v0.x - m) + (v0.y - m) * (v0.y - m) +
        (v0.z - m) * (v0.z - m) + (v0.w - m) * (v0.w - m) +
        (v1.x - m) * (v1.x - m) + (v1.y - m) * (v1.y - m) +
        (v1.z - m) * (v1.z - m) + (v1.w - m) * (v1.w - m);
#pragma unroll
    for (int o = 16; o; o >>= 1) q += __shfl_xor_sync(0xffffffffu, q, o);
    const float rstd = rsqrtf(q * (1.f / E_) + 1e-5f);

    const float4 s0 = ((const float4*)sc)[lane];
    const float4 s1 = ((const float4*)sc)[32 + lane];
    const float4 b0 = ((const float4*)bi)[lane];
    const float4 b1 = ((const float4*)bi)[32 + lane];
    float4 o0, o1;
    o0.x = (v0.x - m) * rstd * s0.x + b0.x;
    o0.y = (v0.y - m) * rstd * s0.y + b0.y;
    o0.z = (v0.z - m) * rstd * s0.z + b0.z;
    o0.w = (v0.w - m) * rstd * s0.w + b0.w;
    o1.x = (v1.x - m) * rstd * s1.x + b1.x;
    o1.y = (v1.y - m) * rstd * s1.y + b1.y;
    o1.z = (v1.z - m) * rstd * s1.z + b1.z;
    o1.w = (v1.w - m) * rstd * s1.w + b1.w;
    ((float4*)out)[base4 + lane]      = o0;
    ((float4*)out)[base4 + 32 + lane] = o1;
}

// ---------------------------------------------------------------------------
// Per-sample sigmoid gate
// ---------------------------------------------------------------------------
__global__ void wu_kernel(const float* __restrict__ feat,
                          const float* __restrict__ W,
                          const float* __restrict__ bias,
                          float* __restrict__ wu) {
    const int b = blockIdx.x * blockDim.x + threadIdx.x;
    if (b < B_) {
        float z = bias[0];
#pragma unroll
        for (int i = 0; i < 13; i++) z += feat[b * 13 + i] * W[i];
        wu[b] = 1.f / (1.f + expf(-z));
    }
}

// ---------------------------------------------------------------------------
// Weighted pool + concat
// ---------------------------------------------------------------------------
__global__ __launch_bounds__(256)
void pool_kernel(const float* __restrict__ x, const float* __restrict__ attr_tf,
                 const int* __restrict__ lens, const int* __restrict__ lens_user,
                 const float* __restrict__ wu,
                 const int* __restrict__ user_ids, const int* __restrict__ item_ids,
                 const float* __restrict__ user_emb, const float* __restrict__ item_emb,
                 float* __restrict__ out) {
    const int b = blockIdx.x;
    const int e = threadIdx.x;
    __shared__ float w[S_];
    if (e < S_) {
        const int s = e;
        float wgt = 0.f;
        if (s < lens[b]) {
            const float g = (s < lens_user[b]) ? wu[b] : (1.f - wu[b]);
            wgt = attr_tf[b * S_ + s] * g;
        }
        w[s] = wgt;
    }
    __syncthreads();
    float acc = 0.f;
    const float* xb = x + (size_t)b * S_ * E_ + e;
    for (int s = 0; s < S_; s++) acc += w[s] * xb[(size_t)s * E_];
    out[(size_t)b * 3 * E_ + E_ + e]     = acc;
    out[(size_t)b * 3 * E_ + e]          = user_emb[(size_t)user_ids[b] * E_ + e];
    out[(size_t)b * 3 * E_ + 2 * E_ + e] = item_emb[(size_t)item_ids[b] * E_ + e];
}

// ---------------------------------------------------------------------------
// Scoring head: one warp per (b, target), float4 dot over 3E=768
// ---------------------------------------------------------------------------
__global__ __launch_bounds__(256)
void logits_kernel(const float* __restrict__ outv, const float* __restrict__ out_emb,
                   const int* __restrict__ pos_t, const int* __restrict__ pos_l,
                   const int* __restrict__ neg_t, const int* __restrict__ neg_l,
                   float* __restrict__ dout) {
    const int gw   = (int)((blockIdx.x * blockDim.x + threadIdx.x) >> 5);
    const int lane = threadIdx.x & 31;
    if (gw >= B_ * NT_) return;
    const int b = gw / NT_;
    const int j = gw % NT_;
    int tgt; float valid, is_pos;
    if (j < P_) {
        tgt = pos_t[b * P_ + j];
        valid = (j < pos_l[b]) ? 1.f : 0.f;
        is_pos = 1.f;
    } else {
        const int jn = j - P_;
        tgt = neg_t[b * N_ + jn];
        valid = (jn < neg_l[b]) ? 1.f : 0.f;
        is_pos = 0.f;
    }
    const float4* er = (const float4*)(out_emb + (size_t)tgt * (3 * E_));
    const float4* ov = (const float4*)(outv + (size_t)b * (3 * E_));
    float acc = 0.f;
#pragma unroll
    for (int i = 0; i < 6; i++) {
        const int k4 = lane + i * 32;
        float4 a = er[k4], c = ov[k4];
        acc += a.x * c.x + a.y * c.y + a.z * c.z + a.w * c.w;
    }
#pragma unroll
    for (int o = 16; o; o >>= 1) acc += __shfl_xor_sync(0xffffffffu, acc, o);
    if (lane == 0) {
        const int idx = b * NT_ + j;
        dout[idx]                 = acc;
        dout[B_ * NT_ + idx]      = valid;
        dout[2 * B_ * NT_ + idx]  = is_pos * valid;
    }
}

// ---------------------------------------------------------------------------
// Launch
// ---------------------------------------------------------------------------
extern "C" void kernel_launch(void* const* d_in, const int* in_sizes, int n_in,
                              void* d_out, int out_size) {
    const int*   attr           = (const int*)  d_in[0];
    const float* attr_tf        = (const float*)d_in[2];
    const float* attr_feat      = (const float*)d_in[3];
    const int*   attr_lens      = (const int*)  d_in[4];
    const int*   attr_lens_user = (const int*)  d_in[5];
    const int*   user_ids       = (const int*)  d_in[7];
    const int*   item_ids       = (const int*)  d_in[8];
    const int*   pos_targets    = (const int*)  d_in[9];
    const int*   pos_lens       = (const int*)  d_in[10];
    const int*   neg_targets    = (const int*)  d_in[11];
    const int*   neg_lens       = (const int*)  d_in[12];
    const float* attr_emb       = (const float*)d_in[13];
    const float* user_emb       = (const float*)d_in[14];
    const float* item_emb       = (const float*)d_in[15];
    const float* out_emb        = (const float*)d_in[16];
    const float* fw_W           = (const float*)d_in[17];
    const float* fw_b           = (const float*)d_in[18];
    const float* qkv_w          = (const float*)d_in[19];
    const float* qkv_b          = (const float*)d_in[20];
    const float* attn_out_w     = (const float*)d_in[21];
    const float* attn_out_b     = (const float*)d_in[22];
    const float* ln1_s          = (const float*)d_in[23];
    const float* ln1_b          = (const float*)d_in[24];
    const float* ff1_w          = (const float*)d_in[25];
    const float* ff1_b          = (const float*)d_in[26];
    const float* ff2_w          = (const float*)d_in[27];
    const float* ff2_b          = (const float*)d_in[28];
    const float* ln2_s          = (const float*)d_in[29];
    const float* ln2_b          = (const float*)d_in[30];

    float *x, *qkv, *attn, *tmp, *ff, *outv, *wu;
    cudaGetSymbolAddress((void**)&x,    g_x);
    cudaGetSymbolAddress((void**)&qkv,  g_qkv);
    cudaGetSymbolAddress((void**)&attn, g_attn);
    cudaGetSymbolAddress((void**)&tmp,  g_tmp);
    cudaGetSymbolAddress((void**)&ff,   g_ff);
    cudaGetSymbolAddress((void**)&outv, g_out);
    cudaGetSymbolAddress((void**)&wu,   g_wu);

    const int gemm_smem = (2 * ASZ + 2 * BSZ) * (int)sizeof(uint32_t);  // 60KB
    cudaFuncSetAttribute(tgemm<false>, cudaFuncAttributeMaxDynamicSharedMemorySize,
                         gemm_smem);
    cudaFuncSetAttribute(tgemm<true>, cudaFuncAttributeMaxDynamicSharedMemorySize,
                         gemm_smem);
    const int attn_smem = (2 * S_ * HD_ + S_ * PLD) * (int)sizeof(float); // ~130KB
    cudaFuncSetAttribute(attn_kernel, cudaFuncAttributeMaxDynamicSharedMemorySize,
                         attn_smem);

    gather_kernel<<<(T_ * E_ / 4 + 255) / 256, 256>>>(attr, attr_emb, x);

    for (int l = 0; l < L_; l++) {
        const float* lqkv_w = qkv_w      + (size_t)l * 3 * E_ * E_;
        const float* lqkv_b = qkv_b      + (size_t)l * 3 * E_;
        const float* lao_w  = attn_out_w + (size_t)l * E_ * E_;
        const float* lao_b  = attn_out_b + (size_t)l * E_;
        const float* l1s    = ln1_s + (size_t)l * E_;
        const float* l1b    = ln1_b + (size_t)l * E_;
        const float* lf1_w  = ff1_w + (size_t)l * F_ * E_;
        const float* lf1_b  = ff1_b + (size_t)l * F_;
        const float* lf2_w  = ff2_w + (size_t)l * E_ * F_;
        const float* lf2_b  = ff2_b + (size_t)l * E_;
        const float* l2s    = ln2_s + (size_t)l * E_;
        const float* l2b    = ln2_b + (size_t)l * E_;

        tgemm<false><<<dim3(3 * E_ / 256, T_ / 128), 256, gemm_smem>>>(
            x, lqkv_w, lqkv_b, qkv, T_, 3 * E_, E_);
        attn_kernel<<<B_ * H_, S_, attn_smem>>>(qkv, attr_lens, attn);
        tgemm<false><<<dim3(E_ / 256, T_ / 128), 256, gemm_smem>>>(
            attn, lao_w, lao_b, tmp, T_, E_, E_);
        add_ln_kernel<<<T_ / 8, 256>>>(x, tmp, l1s, l1b, x);
        tgemm<true><<<dim3(F_ / 256, T_ / 128), 256, gemm_smem>>>(
            x, lf1_w, lf1_b, ff, T_, F_, E_);
        tgemm<false><<<dim3(E_ / 256, T_ / 128), 256, gemm_smem>>>(
            ff, lf2_w, lf2_b, tmp, T_, E_, F_);
        add_ln_kernel<<<T_ / 8, 256>>>(x, tmp, l2s, l2b, x);
    }

    wu_kernel<<<1, 256>>>(attr_feat, fw_W, fw_b, wu);
    pool_kernel<<<B_, 256>>>(x, attr_tf, attr_lens, attr_lens_user, wu,
                             user_ids, item_ids, user_emb, item_emb, outv);

    const int nwarps = B_ * NT_;
    logits_kernel<<<(nwarps * 32 + 255) / 256, 256>>>(
        outv, out_emb, pos_targets, pos_lens, neg_targets, neg_lens,
        (float*)d_out);
}

// round 5
// speedup vs baseline: 3.0192x; 1.0759x over previous
#include <cuda_runtime.h>
#include <cuda_bf16.h>
#include <math.h>
#include <stdint.h>

// Problem constants
#define B_   256
#define S_   128
#define P_   100
#define N_   500
#define E_   256
#define H_   4
#define HD_  64
#define L_   2
#define F_   1024
#define T_   (B_ * S_)      // 32768 tokens
#define NT_  (P_ + N_)      // 600 targets

// ---------------------------------------------------------------------------
// Scratch (device globals — no allocation allowed)
// ---------------------------------------------------------------------------
__device__ float g_x   [(size_t)T_ * E_];
__device__ float g_qkv [(size_t)T_ * 3 * E_];
__device__ float g_attn[(size_t)T_ * E_];
__device__ float g_tmp [(size_t)T_ * E_];
__device__ float g_ff  [(size_t)T_ * F_];
__device__ float g_out [(size_t)B_ * 3 * E_];
__device__ float g_wu  [B_];

// ---------------------------------------------------------------------------
// cp.async helpers
// ---------------------------------------------------------------------------
__device__ __forceinline__ void cp16(void* sdst, const void* gsrc) {
    uint32_t s = (uint32_t)__cvta_generic_to_shared(sdst);
    asm volatile("cp.async.cg.shared.global [%0], [%1], 16;\n" :: "r"(s), "l"(gsrc));
}
__device__ __forceinline__ void cp_commit() {
    asm volatile("cp.async.commit_group;\n");
}
template<int NWait>
__device__ __forceinline__ void cp_wait() {
    asm volatile("cp.async.wait_group %0;\n" :: "n"(NWait));
}

__device__ __forceinline__ uint32_t f2tf32(float x) {
    uint32_t r;
    asm("cvt.rna.tf32.f32 %0, %1;" : "=r"(r) : "f"(x));
    return r;
}

// ---------------------------------------------------------------------------
// Embedding gather (float4)
// ---------------------------------------------------------------------------
__global__ void gather_kernel(const int* __restrict__ attr,
                              const float* __restrict__ emb,
                              float* __restrict__ x) {
    int i4 = blockIdx.x * blockDim.x + threadIdx.x;
    if (i4 < T_ * (E_ / 4)) {
        int t = i4 >> 6;
        int e4 = i4 & 63;
        ((float4*)x)[i4] = ((const float4*)emb)[(size_t)attr[t] * (E_ / 4) + e4];
    }
}

// ---------------------------------------------------------------------------
// TF32 tensor-core GEMM: C[M,N] = A[M,K] @ B[N,K]^T + bias[N] (opt ReLU)
// Block tile 128x256, BK=16, 256 threads (8 warps), warp tile 64x64
// (4x8 grid of m16n8k8 fragments). Smem stride-20 words -> conflict-free
// fragment reads. 3-stage cp.async pipeline (one syncthreads per k-tile).
// Fragments rounded to tf32 with cvt.rna in registers (unbiased).
// Requires M%128==0, N%256==0, K%16==0.
// ---------------------------------------------------------------------------
#define LDA    20
#define ASZ    (128 * LDA)      // one A stage in words
#define BSZ    (256 * LDA)      // one B stage in words
#define STAGES 3

template<bool RELU>
__global__ __launch_bounds__(256)
void tgemm(const float* __restrict__ A, const float* __restrict__ Bm,
           const float* __restrict__ bias, float* __restrict__ C,
           int M, int N, int K) {
    extern __shared__ float smw[];
    float* As = smw;                     // [STAGES][128][LDA]
    float* Bs = smw + STAGES * ASZ;      // [STAGES][256][LDA]

    const int bm   = blockIdx.y * 128;
    const int bn   = blockIdx.x * 256;
    const int t    = threadIdx.x;
    const int lane = t & 31;
    const int wid  = t >> 5;
    const int wm   = (wid & 1) * 64;
    const int wn   = (wid >> 1) * 64;
    const int g    = lane >> 2;
    const int tg   = lane & 3;

    const int arow = t >> 1;
    const int akb  = (t & 1) * 8;
    const float* Ap = A  + (size_t)(bm + arow) * K + akb;
    const float* Bp = Bm + (size_t)(bn + t) * K;

    float acc[4][8][4];
#pragma unroll
    for (int i = 0; i < 4; i++)
#pragma unroll
        for (int j = 0; j < 8; j++)
#pragma unroll
            for (int r = 0; r < 4; r++) acc[i][j][r] = 0.f;

    const int nk = K >> 4;

    // prologue: stages 0..STAGES-2
#pragma unroll
    for (int s = 0; s < STAGES - 1; s++) {
        const int k0 = s << 4;
        cp16(&As[s * ASZ + arow * LDA + akb],     Ap + k0);
        cp16(&As[s * ASZ + arow * LDA + akb + 4], Ap + k0 + 4);
#pragma unroll
        for (int j = 0; j < 4; j++)
            cp16(&Bs[s * BSZ + t * LDA + j * 4], Bp + k0 + j * 4);
        cp_commit();
    }

    int cur = 0;
    for (int kt = 0; kt < nk; kt++) {
        if (kt < nk - 1) cp_wait<STAGES - 2>(); else cp_wait<0>();
        __syncthreads();

        const float* Ac = As + cur * ASZ;
        const float* Bc = Bs + cur * BSZ;
#pragma unroll
        for (int ks = 0; ks < 2; ks++) {
            const int k0 = ks * 8;
            uint32_t af[4][4], bf[8][2];
#pragma unroll
            for (int mf = 0; mf < 4; mf++) {
                const int row = wm + mf * 16 + g;
                af[mf][0] = f2tf32(Ac[row * LDA + k0 + tg]);
                af[mf][1] = f2tf32(Ac[(row + 8) * LDA + k0 + tg]);
                af[mf][2] = f2tf32(Ac[row * LDA + k0 + tg + 4]);
                af[mf][3] = f2tf32(Ac[(row + 8) * LDA + k0 + tg + 4]);
            }
#pragma unroll
            for (int nf = 0; nf < 8; nf++) {
                const int col = wn + nf * 8 + g;
                bf[nf][0] = f2tf32(Bc[col * LDA + k0 + tg]);
                bf[nf][1] = f2tf32(Bc[col * LDA + k0 + tg + 4]);
            }
#pragma unroll
            for (int mf = 0; mf < 4; mf++)
#pragma unroll
                for (int nf = 0; nf < 8; nf++) {
                    float* d = acc[mf][nf];
                    asm volatile(
                        "mma.sync.aligned.m16n8k8.row.col.f32.tf32.tf32.f32 "
                        "{%0,%1,%2,%3}, {%4,%5,%6,%7}, {%8,%9}, {%0,%1,%2,%3};"
                        : "+f"(d[0]), "+f"(d[1]), "+f"(d[2]), "+f"(d[3])
                        : "r"(af[mf][0]), "r"(af[mf][1]), "r"(af[mf][2]),
                          "r"(af[mf][3]), "r"(bf[nf][0]), "r"(bf[nf][1]));
                }
        }

        const int pf = kt + STAGES - 1;
        if (pf < nk) {
            const int ps = pf % STAGES;
            const int k0 = pf << 4;
            cp16(&As[ps * ASZ + arow * LDA + akb],     Ap + k0);
            cp16(&As[ps * ASZ + arow * LDA + akb + 4], Ap + k0 + 4);
#pragma unroll
            for (int j = 0; j < 4; j++)
                cp16(&Bs[ps * BSZ + t * LDA + j * 4], Bp + k0 + j * 4);
            cp_commit();
        }
        cur = (cur + 1 == STAGES) ? 0 : cur + 1;
    }

    // epilogue: bias (+ReLU), float2 stores
#pragma unroll
    for (int nf = 0; nf < 8; nf++) {
        const int col = bn + wn + nf * 8 + 2 * tg;
        const float b0v = bias[col], b1v = bias[col + 1];
#pragma unroll
        for (int mf = 0; mf < 4; mf++) {
            const int row = bm + wm + mf * 16 + g;
            float v0 = acc[mf][nf][0] + b0v;
            float v1 = acc[mf][nf][1] + b1v;
            float v2 = acc[mf][nf][2] + b0v;
            float v3 = acc[mf][nf][3] + b1v;
            if (RELU) {
                v0 = fmaxf(v0, 0.f); v1 = fmaxf(v1, 0.f);
                v2 = fmaxf(v2, 0.f); v3 = fmaxf(v3, 0.f);
            }
            *(float2*)(C + (size_t)row * N + col)       = make_float2(v0, v1);
            *(float2*)(C + (size_t)(row + 8) * N + col) = make_float2(v2, v3);
        }
    }
}

// ---------------------------------------------------------------------------
// Attention v3: one block per (b,h), 128 threads (thread = query row).
// Single pass: p = exp(score) without max subtraction (scores are O(1) here;
// identical math, softmax is shift-invariant), masked keys skipped by
// looping k < len. Only K/V in smem (64KB) -> 3 CTAs/SM, 12 warps/SM.
// ---------------------------------------------------------------------------
__global__ __launch_bounds__(128)
void attn_kernel(const float* __restrict__ qkv,
                 const int* __restrict__ lens,
                 float* __restrict__ out) {
    const int bh = blockIdx.x;
    const int b  = bh / H_;
    const int h  = bh % H_;
    extern __shared__ float sm[];
    float* Ks = sm;                        // [128][64]
    float* Vs = sm + S_ * HD_;             // [128][64]

    for (int i4 = threadIdx.x; i4 < S_ * HD_ / 4; i4 += blockDim.x) {
        const int s  = i4 >> 4;
        const int d4 = i4 & 15;
        const float4* base =
            (const float4*)(qkv + (size_t)(b * S_ + s) * (3 * E_) + h * HD_);
        ((float4*)Ks)[i4] = base[(E_ / 4) + d4];
        ((float4*)Vs)[i4] = base[(2 * E_ / 4) + d4];
    }
    __syncthreads();

    const int q   = threadIdx.x;
    const int len = lens[b];

    float4 qr[16];
    {
        const float4* qp =
            (const float4*)(qkv + (size_t)(b * S_ + q) * (3 * E_) + h * HD_);
#pragma unroll
        for (int d = 0; d < 16; d++) qr[d] = qp[d];
    }

    float4 acc[16];
#pragma unroll
    for (int d = 0; d < 16; d++) acc[d] = make_float4(0.f, 0.f, 0.f, 0.f);
    float sum = 0.f;

    for (int k = 0; k < len; k++) {
        const float4* kp = (const float4*)(Ks + k * HD_);
        // 4 partial sums -> shorter dependency chains
        float s0 = 0.f, s1 = 0.f, s2 = 0.f, s3 = 0.f;
#pragma unroll
        for (int d = 0; d < 16; d += 4) {
            float4 k0 = kp[d], k1 = kp[d + 1], k2 = kp[d + 2], k3 = kp[d + 3];
            s0 += qr[d].x     * k0.x + qr[d].y     * k0.y + qr[d].z     * k0.z + qr[d].w     * k0.w;
            s1 += qr[d + 1].x * k1.x + qr[d + 1].y * k1.y + qr[d + 1].z * k1.z + qr[d + 1].w * k1.w;
            s2 += qr[d + 2].x * k2.x + qr[d + 2].y * k2.y + qr[d + 2].z * k2.z + qr[d + 2].w * k2.w;
            s3 += qr[d + 3].x * k3.x + qr[d + 3].y * k3.y + qr[d + 3].z * k3.z + qr[d + 3].w * k3.w;
        }
        const float p = __expf(((s0 + s1) + (s2 + s3)) * 0.125f);
        sum += p;
        const float4* vp = (const float4*)(Vs + k * HD_);
#pragma unroll
        for (int d = 0; d < 16; d++) {
            float4 vv = vp[d];
            acc[d].x += p * vv.x; acc[d].y += p * vv.y;
            acc[d].z += p * vv.z; acc[d].w += p * vv.w;
        }
    }
    const float inv = 1.f / sum;
    float4* op = (float4*)(out + (size_t)(b * S_ + q) * E_ + h * HD_);
#pragma unroll
    for (int d = 0; d < 16; d++) {
        float4 a = acc[d];
        a.x *= inv; a.y *= inv; a.z *= inv; a.w *= inv;
        op[d] = a;
    }
}

// ---------------------------------------------------------------------------
// Fused residual add + LayerNorm: warp per token, 8 tokens per block
// ---------------------------------------------------------------------------
__global__ __launch_bounds__(256)
void add_ln_kernel(const float* __restrict__ x, const float* __restrict__ y,
                   const float* __restrict__ sc, const float* __restrict__ bi,
                   float* __restrict__ out) {
    const int tok  = blockIdx.x * 8 + (threadIdx.x >> 5);
    const int lane = threadIdx.x & 31;
    const size_t base4 = (size_t)tok * (E_ / 4);

    float4 v0 = ((const float4*)x)[base4 + lane];
    float4 v1 = ((const float4*)x)[base4 + 32 + lane];
    float4 y0 = ((const float4*)y)[base4 + lane];
    float4 y1 = ((const float4*)y)[base4 + 32 + lane];
    v0.x += y0.x; v0.y += y0.y; v0.z += y0.z; v0.w += y0.w;
    v1.x += y1.x; v1.y += y1.y; v1.z += y1.z; v1.w += y1.w;

    float s = v0.x + v0.y + v0.z + v0.w + v1.x + v1.y + v1.z + v1.w;
#pragma unroll
    for (int o = 16; o; o >>= 1) s += __shfl_xor_sync(0xffffffffu, s, o);
    const float m = s * (1.f / E_);

    float q =
        (v0.x - m) * (v0.x - m) + (v0.y - m) * (v0.y - m) +
        (v0.z - m) * (v0.z - m) + (v0.w - m) * (v0.w - m) +
        (v1.x - m) * (v1.x - m) + (v1.y - m) * (v1.y - m) +
        (v1.z - m) * (v1.z - m) + (v1.w - m) * (v1.w - m);
#pragma unroll
    for (int o = 16; o; o >>= 1) q += __shfl_xor_sync(0xffffffffu, q, o);
    const float rstd = rsqrtf(q * (1.f / E_) + 1e-5f);

    const float4 s0 = ((const float4*)sc)[lane];
    const float4 s1 = ((const float4*)sc)[32 + lane];
    const float4 b0 = ((const float4*)bi)[lane];
    const float4 b1 = ((const float4*)bi)[32 + lane];
    float4 o0, o1;
    o0.x = (v0.x - m) * rstd * s0.x + b0.x;
    o0.y = (v0.y - m) * rstd * s0.y + b0.y;
    o0.z = (v0.z - m) * rstd * s0.z + b0.z;
    o0.w = (v0.w - m) * rstd * s0.w + b0.w;
    o1.x = (v1.x - m) * rstd * s1.x + b1.x;
    o1.y = (v1.y - m) * rstd * s1.y + b1.y;
    o1.z = (v1.z - m) * rstd * s1.z + b1.z;
    o1.w = (v1.w - m) * rstd * s1.w + b1.w;
    ((float4*)out)[base4 + lane]      = o0;
    ((float4*)out)[base4 + 32 + lane] = o1;
}

// ---------------------------------------------------------------------------
// Per-sample sigmoid gate
// ---------------------------------------------------------------------------
__global__ void wu_kernel(const float* __restrict__ feat,
                          const float* __restrict__ W,
                          const float* __restrict__ bias,
                          float* __restrict__ wu) {
    const int b = blockIdx.x * blockDim.x + threadIdx.x;
    if (b < B_) {
        float z = bias[0];
#pragma unroll
        for (int i = 0; i < 13; i++) z += feat[b * 13 + i] * W[i];
        wu[b] = 1.f / (1.f + expf(-z));
    }
}

// ---------------------------------------------------------------------------
// Weighted pool + concat
// ---------------------------------------------------------------------------
__global__ __launch_bounds__(256)
void pool_kernel(const float* __restrict__ x, const float* __restrict__ attr_tf,
                 const int* __restrict__ lens, const int* __restrict__ lens_user,
                 const float* __restrict__ wu,
                 const int* __restrict__ user_ids, const int* __restrict__ item_ids,
                 const float* __restrict__ user_emb, const float* __restrict__ item_emb,
                 float* __restrict__ out) {
    const int b = blockIdx.x;
    const int e = threadIdx.x;
    __shared__ float w[S_];
    if (e < S_) {
        const int s = e;
        float wgt = 0.f;
        if (s < lens[b]) {
            const float g = (s < lens_user[b]) ? wu[b] : (1.f - wu[b]);
            wgt = attr_tf[b * S_ + s] * g;
        }
        w[s] = wgt;
    }
    __syncthreads();
    float acc = 0.f;
    const float* xb = x + (size_t)b * S_ * E_ + e;
    for (int s = 0; s < S_; s++) acc += w[s] * xb[(size_t)s * E_];
    out[(size_t)b * 3 * E_ + E_ + e]     = acc;
    out[(size_t)b * 3 * E_ + e]          = user_emb[(size_t)user_ids[b] * E_ + e];
    out[(size_t)b * 3 * E_ + 2 * E_ + e] = item_emb[(size_t)item_ids[b] * E_ + e];
}

// ---------------------------------------------------------------------------
// Scoring head: one warp per (b, target), float4 dot over 3E=768
// ---------------------------------------------------------------------------
__global__ __launch_bounds__(256)
void logits_kernel(const float* __restrict__ outv, const float* __restrict__ out_emb,
                   const int* __restrict__ pos_t, const int* __restrict__ pos_l,
                   const int* __restrict__ neg_t, const int* __restrict__ neg_l,
                   float* __restrict__ dout) {
    const int gw   = (int)((blockIdx.x * blockDim.x + threadIdx.x) >> 5);
    const int lane = threadIdx.x & 31;
    if (gw >= B_ * NT_) return;
    const int b = gw / NT_;
    const int j = gw % NT_;
    int tgt; float valid, is_pos;
    if (j < P_) {
        tgt = pos_t[b * P_ + j];
        valid = (j < pos_l[b]) ? 1.f : 0.f;
        is_pos = 1.f;
    } else {
        const int jn = j - P_;
        tgt = neg_t[b * N_ + jn];
        valid = (jn < neg_l[b]) ? 1.f : 0.f;
        is_pos = 0.f;
    }
    const float4* er = (const float4*)(out_emb + (size_t)tgt * (3 * E_));
    const float4* ov = (const float4*)(outv + (size_t)b * (3 * E_));
    float acc = 0.f;
#pragma unroll
    for (int i = 0; i < 6; i++) {
        const int k4 = lane + i * 32;
        float4 a = er[k4], c = ov[k4];
        acc += a.x * c.x + a.y * c.y + a.z * c.z + a.w * c.w;
    }
#pragma unroll
    for (int o = 16; o; o >>= 1) acc += __shfl_xor_sync(0xffffffffu, acc, o);
    if (lane == 0) {
        const int idx = b * NT_ + j;
        dout[idx]                 = acc;
        dout[B_ * NT_ + idx]      = valid;
        dout[2 * B_ * NT_ + idx]  = is_pos * valid;
    }
}

// ---------------------------------------------------------------------------
// Launch
// ---------------------------------------------------------------------------
extern "C" void kernel_launch(void* const* d_in, const int* in_sizes, int n_in,
                              void* d_out, int out_size) {
    const int*   attr           = (const int*)  d_in[0];
    const float* attr_tf        = (const float*)d_in[2];
    const float* attr_feat      = (const float*)d_in[3];
    const int*   attr_lens      = (const int*)  d_in[4];
    const int*   attr_lens_user = (const int*)  d_in[5];
    const int*   user_ids       = (const int*)  d_in[7];
    const int*   item_ids       = (const int*)  d_in[8];
    const int*   pos_targets    = (const int*)  d_in[9];
    const int*   pos_lens       = (const int*)  d_in[10];
    const int*   neg_targets    = (const int*)  d_in[11];
    const int*   neg_lens       = (const int*)  d_in[12];
    const float* attr_emb       = (const float*)d_in[13];
    const float* user_emb       = (const float*)d_in[14];
    const float* item_emb       = (const float*)d_in[15];
    const float* out_emb        = (const float*)d_in[16];
    const float* fw_W           = (const float*)d_in[17];
    const float* fw_b           = (const float*)d_in[18];
    const float* qkv_w          = (const float*)d_in[19];
    const float* qkv_b          = (const float*)d_in[20];
    const float* attn_out_w     = (const float*)d_in[21];
    const float* attn_out_b     = (const float*)d_in[22];
    const float* ln1_s          = (const float*)d_in[23];
    const float* ln1_b          = (const float*)d_in[24];
    const float* ff1_w          = (const float*)d_in[25];
    const float* ff1_b          = (const float*)d_in[26];
    const float* ff2_w          = (const float*)d_in[27];
    const float* ff2_b          = (const float*)d_in[28];
    const float* ln2_s          = (const float*)d_in[29];
    const float* ln2_b          = (const float*)d_in[30];

    float *x, *qkv, *attn, *tmp, *ff, *outv, *wu;
    cudaGetSymbolAddress((void**)&x,    g_x);
    cudaGetSymbolAddress((void**)&qkv,  g_qkv);
    cudaGetSymbolAddress((void**)&attn, g_attn);
    cudaGetSymbolAddress((void**)&tmp,  g_tmp);
    cudaGetSymbolAddress((void**)&ff,   g_ff);
    cudaGetSymbolAddress((void**)&outv, g_out);
    cudaGetSymbolAddress((void**)&wu,   g_wu);

    const int gemm_smem = STAGES * (ASZ + BSZ) * (int)sizeof(float);  // 92160B
    cudaFuncSetAttribute(tgemm<false>, cudaFuncAttributeMaxDynamicSharedMemorySize,
                         gemm_smem);
    cudaFuncSetAttribute(tgemm<true>, cudaFuncAttributeMaxDynamicSharedMemorySize,
                         gemm_smem);
    const int attn_smem = 2 * S_ * HD_ * (int)sizeof(float);          // 64KB
    cudaFuncSetAttribute(attn_kernel, cudaFuncAttributeMaxDynamicSharedMemorySize,
                         attn_smem);

    gather_kernel<<<(T_ * E_ / 4 + 255) / 256, 256>>>(attr, attr_emb, x);

    for (int l = 0; l < L_; l++) {
        const float* lqkv_w = qkv_w      + (size_t)l * 3 * E_ * E_;
        const float* lqkv_b = qkv_b      + (size_t)l * 3 * E_;
        const float* lao_w  = attn_out_w + (size_t)l * E_ * E_;
        const float* lao_b  = attn_out_b + (size_t)l * E_;
        const float* l1s    = ln1_s + (size_t)l * E_;
        const float* l1b    = ln1_b + (size_t)l * E_;
        const float* lf1_w  = ff1_w + (size_t)l * F_ * E_;
        const float* lf1_b  = ff1_b + (size_t)l * F_;
        const float* lf2_w  = ff2_w + (size_t)l * E_ * F_;
        const float* lf2_b  = ff2_b + (size_t)l * E_;
        const float* l2s    = ln2_s + (size_t)l * E_;
        const float* l2b    = ln2_b + (size_t)l * E_;

        tgemm<false><<<dim3(3 * E_ / 256, T_ / 128), 256, gemm_smem>>>(
            x, lqkv_w, lqkv_b, qkv, T_, 3 * E_, E_);
        attn_kernel<<<B_ * H_, S_, attn_smem>>>(qkv, attr_lens, attn);
        tgemm<false><<<dim3(E_ / 256, T_ / 128), 256, gemm_smem>>>(
            attn, lao_w, lao_b, tmp, T_, E_, E_);
        add_ln_kernel<<<T_ / 8, 256>>>(x, tmp, l1s, l1b, x);
        tgemm<true><<<dim3(F_ / 256, T_ / 128), 256, gemm_smem>>>(
            x, lf1_w, lf1_b, ff, T_, F_, E_);
        tgemm<false><<<dim3(E_ / 256, T_ / 128), 256, gemm_smem>>>(
            ff, lf2_w, lf2_b, tmp, T_, E_, F_);
        add_ln_kernel<<<T_ / 8, 256>>>(x, tmp, l2s, l2b, x);
    }

    wu_kernel<<<1, 256>>>(attr_feat, fw_W, fw_b, wu);
    pool_kernel<<<B_, 256>>>(x, attr_tf, attr_lens, attr_lens_user, wu,
                             user_ids, item_ids, user_emb, item_emb, outv);

    const int nwarps = B_ * NT_;
    logits_kernel<<<(nwarps * 32 + 255) / 256, 256>>>(
        outv, out_emb, pos_targets, pos_lens, neg_targets, neg_lens,
        (float*)d_out);
}

// round 6
// speedup vs baseline: 3.2941x; 1.0910x over previous
#include <cuda_runtime.h>
#include <cuda_bf16.h>
#include <math.h>
#include <stdint.h>

// Problem constants
#define B_   256
#define S_   128
#define P_   100
#define N_   500
#define E_   256
#define H_   4
#define HD_  64
#define L_   2
#define F_   1024
#define T_   (B_ * S_)      // 32768 tokens
#define NT_  (P_ + N_)      // 600 targets

// ---------------------------------------------------------------------------
// Scratch (device globals — no allocation allowed)
// ---------------------------------------------------------------------------
__device__ float g_x   [(size_t)T_ * E_];
__device__ float g_qkv [(size_t)T_ * 3 * E_];
__device__ float g_attn[(size_t)T_ * E_];
__device__ float g_tmp [(size_t)T_ * E_];
__device__ float g_ff  [(size_t)T_ * F_];
__device__ float g_out [(size_t)B_ * 3 * E_];

// ---------------------------------------------------------------------------
// cp.async helpers
// ---------------------------------------------------------------------------
__device__ __forceinline__ void cp16(void* sdst, const void* gsrc) {
    uint32_t s = (uint32_t)__cvta_generic_to_shared(sdst);
    asm volatile("cp.async.cg.shared.global [%0], [%1], 16;\n" :: "r"(s), "l"(gsrc));
}
__device__ __forceinline__ void cp_commit() {
    asm volatile("cp.async.commit_group;\n");
}
template<int NWait>
__device__ __forceinline__ void cp_wait() {
    asm volatile("cp.async.wait_group %0;\n" :: "n"(NWait));
}

__device__ __forceinline__ uint32_t f2tf32(float x) {
    uint32_t r;
    asm("cvt.rna.tf32.f32 %0, %1;" : "=r"(r) : "f"(x));
    return r;
}

// ---------------------------------------------------------------------------
// Embedding gather (float4)
// ---------------------------------------------------------------------------
__global__ void gather_kernel(const int* __restrict__ attr,
                              const float* __restrict__ emb,
                              float* __restrict__ x) {
    int i4 = blockIdx.x * blockDim.x + threadIdx.x;
    if (i4 < T_ * (E_ / 4)) {
        int t = i4 >> 6;
        int e4 = i4 & 63;
        ((float4*)x)[i4] = ((const float4*)emb)[(size_t)attr[t] * (E_ / 4) + e4];
    }
}

// ---------------------------------------------------------------------------
// TF32 tensor-core GEMM: C[M,N] = A[M,K] @ B[N,K]^T + bias[N] (opt ReLU)
// Block tile 128x128, BK=16, 256 threads (8 warps), warp tile 64x32
// (4x4 grid of m16n8k8 fragments). acc = 64 regs/thread -> <=128 regs ->
// 2 CTAs/SM (25% occ). 3-stage cp.async pipeline, stride-20 smem (conflict-
// free fragment reads). Fragments rounded to tf32 with cvt.rna (unbiased).
// Requires M%128==0, N%128==0, K%16==0.
// ---------------------------------------------------------------------------
#define LDA    20
#define TSZ    (128 * LDA)      // one stage of one matrix, in words
#define STAGES 3

template<bool RELU>
__global__ __launch_bounds__(256, 2)
void tgemm(const float* __restrict__ A, const float* __restrict__ Bm,
           const float* __restrict__ bias, float* __restrict__ C,
           int M, int N, int K) {
    extern __shared__ float smw[];
    float* As = smw;                     // [STAGES][128][LDA]
    float* Bs = smw + STAGES * TSZ;      // [STAGES][128][LDA]

    const int bm   = blockIdx.y * 128;
    const int bn   = blockIdx.x * 128;
    const int t    = threadIdx.x;
    const int lane = t & 31;
    const int wid  = t >> 5;
    const int wm   = (wid & 1) * 64;
    const int wn   = (wid >> 1) * 32;
    const int g    = lane >> 2;
    const int tg   = lane & 3;

    const int lrow = t >> 1;            // 0..127
    const int lkb  = (t & 1) * 8;       // 0 or 8
    const float* Ap = A  + (size_t)(bm + lrow) * K + lkb;
    const float* Bp = Bm + (size_t)(bn + lrow) * K + lkb;

    float acc[4][4][4];
#pragma unroll
    for (int i = 0; i < 4; i++)
#pragma unroll
        for (int j = 0; j < 4; j++)
#pragma unroll
            for (int r = 0; r < 4; r++) acc[i][j][r] = 0.f;

    const int nk = K >> 4;

    // prologue: stages 0..STAGES-2
#pragma unroll
    for (int s = 0; s < STAGES - 1; s++) {
        const int k0 = s << 4;
        cp16(&As[s * TSZ + lrow * LDA + lkb],     Ap + k0);
        cp16(&As[s * TSZ + lrow * LDA + lkb + 4], Ap + k0 + 4);
        cp16(&Bs[s * TSZ + lrow * LDA + lkb],     Bp + k0);
        cp16(&Bs[s * TSZ + lrow * LDA + lkb + 4], Bp + k0 + 4);
        cp_commit();
    }

    int cur = 0;
    for (int kt = 0; kt < nk; kt++) {
        if (kt < nk - 1) cp_wait<STAGES - 2>(); else cp_wait<0>();
        __syncthreads();

        const float* Ac = As + cur * TSZ;
        const float* Bc = Bs + cur * TSZ;
#pragma unroll
        for (int ks = 0; ks < 2; ks++) {
            const int k0 = ks * 8;
            uint32_t af[4][4], bf[4][2];
#pragma unroll
            for (int mf = 0; mf < 4; mf++) {
                const int row = wm + mf * 16 + g;
                af[mf][0] = f2tf32(Ac[row * LDA + k0 + tg]);
                af[mf][1] = f2tf32(Ac[(row + 8) * LDA + k0 + tg]);
                af[mf][2] = f2tf32(Ac[row * LDA + k0 + tg + 4]);
                af[mf][3] = f2tf32(Ac[(row + 8) * LDA + k0 + tg + 4]);
            }
#pragma unroll
            for (int nf = 0; nf < 4; nf++) {
                const int col = wn + nf * 8 + g;
                bf[nf][0] = f2tf32(Bc[col * LDA + k0 + tg]);
                bf[nf][1] = f2tf32(Bc[col * LDA + k0 + tg + 4]);
            }
#pragma unroll
            for (int mf = 0; mf < 4; mf++)
#pragma unroll
                for (int nf = 0; nf < 4; nf++) {
                    float* d = acc[mf][nf];
                    asm volatile(
                        "mma.sync.aligned.m16n8k8.row.col.f32.tf32.tf32.f32 "
                        "{%0,%1,%2,%3}, {%4,%5,%6,%7}, {%8,%9}, {%0,%1,%2,%3};"
                        : "+f"(d[0]), "+f"(d[1]), "+f"(d[2]), "+f"(d[3])
                        : "r"(af[mf][0]), "r"(af[mf][1]), "r"(af[mf][2]),
                          "r"(af[mf][3]), "r"(bf[nf][0]), "r"(bf[nf][1]));
                }
        }

        const int pf = kt + STAGES - 1;
        if (pf < nk) {
            const int ps = pf % STAGES;
            const int k0 = pf << 4;
            cp16(&As[ps * TSZ + lrow * LDA + lkb],     Ap + k0);
            cp16(&As[ps * TSZ + lrow * LDA + lkb + 4], Ap + k0 + 4);
            cp16(&Bs[ps * TSZ + lrow * LDA + lkb],     Bp + k0);
            cp16(&Bs[ps * TSZ + lrow * LDA + lkb + 4], Bp + k0 + 4);
            cp_commit();
        }
        cur = (cur + 1 == STAGES) ? 0 : cur + 1;
    }

    // epilogue: bias (+ReLU), float2 stores
#pragma unroll
    for (int nf = 0; nf < 4; nf++) {
        const int col = bn + wn + nf * 8 + 2 * tg;
        const float b0v = bias[col], b1v = bias[col + 1];
#pragma unroll
        for (int mf = 0; mf < 4; mf++) {
            const int row = bm + wm + mf * 16 + g;
            float v0 = acc[mf][nf][0] + b0v;
            float v1 = acc[mf][nf][1] + b1v;
            float v2 = acc[mf][nf][2] + b0v;
            float v3 = acc[mf][nf][3] + b1v;
            if (RELU) {
                v0 = fmaxf(v0, 0.f); v1 = fmaxf(v1, 0.f);
                v2 = fmaxf(v2, 0.f); v3 = fmaxf(v3, 0.f);
            }
            *(float2*)(C + (size_t)row * N + col)       = make_float2(v0, v1);
            *(float2*)(C + (size_t)(row + 8) * N + col) = make_float2(v2, v3);
        }
    }
}

// ---------------------------------------------------------------------------
// Attention v3: one block per (b,h), 128 threads (thread = query row).
// Single pass, no max subtraction (scores are O(1) here; shift-invariant),
// masked keys skipped by looping k < len. K/V in smem (64KB) -> 3 CTAs/SM.
// ---------------------------------------------------------------------------
__global__ __launch_bounds__(128)
void attn_kernel(const float* __restrict__ qkv,
                 const int* __restrict__ lens,
                 float* __restrict__ out) {
    const int bh = blockIdx.x;
    const int b  = bh / H_;
    const int h  = bh % H_;
    extern __shared__ float sm[];
    float* Ks = sm;                        // [128][64]
    float* Vs = sm + S_ * HD_;             // [128][64]

    for (int i4 = threadIdx.x; i4 < S_ * HD_ / 4; i4 += blockDim.x) {
        const int s  = i4 >> 4;
        const int d4 = i4 & 15;
        const float4* base =
            (const float4*)(qkv + (size_t)(b * S_ + s) * (3 * E_) + h * HD_);
        ((float4*)Ks)[i4] = base[(E_ / 4) + d4];
        ((float4*)Vs)[i4] = base[(2 * E_ / 4) + d4];
    }
    __syncthreads();

    const int q   = threadIdx.x;
    const int len = lens[b];

    float4 qr[16];
    {
        const float4* qp =
            (const float4*)(qkv + (size_t)(b * S_ + q) * (3 * E_) + h * HD_);
#pragma unroll
        for (int d = 0; d < 16; d++) qr[d] = qp[d];
    }

    float4 acc[16];
#pragma unroll
    for (int d = 0; d < 16; d++) acc[d] = make_float4(0.f, 0.f, 0.f, 0.f);
    float sum = 0.f;

    for (int k = 0; k < len; k++) {
        const float4* kp = (const float4*)(Ks + k * HD_);
        float s0 = 0.f, s1 = 0.f, s2 = 0.f, s3 = 0.f;
#pragma unroll
        for (int d = 0; d < 16; d += 4) {
            float4 k0 = kp[d], k1 = kp[d + 1], k2 = kp[d + 2], k3 = kp[d + 3];
            s0 += qr[d].x     * k0.x + qr[d].y     * k0.y + qr[d].z     * k0.z + qr[d].w     * k0.w;
            s1 += qr[d + 1].x * k1.x + qr[d + 1].y * k1.y + qr[d + 1].z * k1.z + qr[d + 1].w * k1.w;
            s2 += qr[d + 2].x * k2.x + qr[d + 2].y * k2.y + qr[d + 2].z * k2.z + qr[d + 2].w * k2.w;
            s3 += qr[d + 3].x * k3.x + qr[d + 3].y * k3.y + qr[d + 3].z * k3.z + qr[d + 3].w * k3.w;
        }
        const float p = __expf(((s0 + s1) + (s2 + s3)) * 0.125f);
        sum += p;
        const float4* vp = (const float4*)(Vs + k * HD_);
#pragma unroll
        for (int d = 0; d < 16; d++) {
            float4 vv = vp[d];
            acc[d].x += p * vv.x; acc[d].y += p * vv.y;
            acc[d].z += p * vv.z; acc[d].w += p * vv.w;
        }
    }
    const float inv = 1.f / sum;
    float4* op = (float4*)(out + (size_t)(b * S_ + q) * E_ + h * HD_);
#pragma unroll
    for (int d = 0; d < 16; d++) {
        float4 a = acc[d];
        a.x *= inv; a.y *= inv; a.z *= inv; a.w *= inv;
        op[d] = a;
    }
}

// ---------------------------------------------------------------------------
// Fused residual add + LayerNorm: warp per token, 8 tokens per block
// ---------------------------------------------------------------------------
__global__ __launch_bounds__(256)
void add_ln_kernel(const float* __restrict__ x, const float* __restrict__ y,
                   const float* __restrict__ sc, const float* __restrict__ bi,
                   float* __restrict__ out) {
    const int tok  = blockIdx.x * 8 + (threadIdx.x >> 5);
    const int lane = threadIdx.x & 31;
    const size_t base4 = (size_t)tok * (E_ / 4);

    float4 v0 = ((const float4*)x)[base4 + lane];
    float4 v1 = ((const float4*)x)[base4 + 32 + lane];
    float4 y0 = ((const float4*)y)[base4 + lane];
    float4 y1 = ((const float4*)y)[base4 + 32 + lane];
    v0.x += y0.x; v0.y += y0.y; v0.z += y0.z; v0.w += y0.w;
    v1.x += y1.x; v1.y += y1.y; v1.z += y1.z; v1.w += y1.w;

    float s = v0.x + v0.y + v0.z + v0.w + v1.x + v1.y + v1.z + v1.w;
#pragma unroll
    for (int o = 16; o; o >>= 1) s += __shfl_xor_sync(0xffffffffu, s, o);
    const float m = s * (1.f / E_);

    float q =
        (v0.x - m) * (v0.x - m) + (v0.y - m) * (v0.y - m) +
        (v0.z - m) * (v0.z - m) + (v0.w - m) * (v0.w - m) +
        (v1.x - m) * (v1.x - m) + (v1.y - m) * (v1.y - m) +
        (v1.z - m) * (v1.z - m) + (v1.w - m) * (v1.w - m);
#pragma unroll
    for (int o = 16; o; o >>= 1) q += __shfl_xor_sync(0xffffffffu, q, o);
    const float rstd = rsqrtf(q * (1.f / E_) + 1e-5f);

    const float4 s0 = ((const float4*)sc)[lane];
    const float4 s1 = ((const float4*)sc)[32 + lane];
    const float4 b0 = ((const float4*)bi)[lane];
    const float4 b1 = ((const float4*)bi)[32 + lane];
    float4 o0, o1;
    o0.x = (v0.x - m) * rstd * s0.x + b0.x;
    o0.y = (v0.y - m) * rstd * s0.y + b0.y;
    o0.z = (v0.z - m) * rstd * s0.z + b0.z;
    o0.w = (v0.w - m) * rstd * s0.w + b0.w;
    o1.x = (v1.x - m) * rstd * s1.x + b1.x;
    o1.y = (v1.y - m) * rstd * s1.y + b1.y;
    o1.z = (v1.z - m) * rstd * s1.z + b1.z;
    o1.w = (v1.w - m) * rstd * s1.w + b1.w;
    ((float4*)out)[base4 + lane]      = o0;
    ((float4*)out)[base4 + 32 + lane] = o1;
}

// ---------------------------------------------------------------------------
// Weighted pool + concat (+ per-sample sigmoid gate computed in-block)
// ---------------------------------------------------------------------------
__global__ __launch_bounds__(256)
void pool_kernel(const float* __restrict__ x, const float* __restrict__ attr_tf,
                 const int* __restrict__ lens, const int* __restrict__ lens_user,
                 const float* __restrict__ feat, const float* __restrict__ fW,
                 const float* __restrict__ fb,
                 const int* __restrict__ user_ids, const int* __restrict__ item_ids,
                 const float* __restrict__ user_emb, const float* __restrict__ item_emb,
                 float* __restrict__ out) {
    const int b = blockIdx.x;
    const int e = threadIdx.x;
    __shared__ float w[S_];
    __shared__ float wu_s;
    if (e == 0) {
        float z = fb[0];
#pragma unroll
        for (int i = 0; i < 13; i++) z += feat[b * 13 + i] * fW[i];
        wu_s = 1.f / (1.f + expf(-z));
    }
    __syncthreads();
    if (e < S_) {
        const int s = e;
        float wgt = 0.f;
        if (s < lens[b]) {
            const float g = (s < lens_user[b]) ? wu_s : (1.f - wu_s);
            wgt = attr_tf[b * S_ + s] * g;
        }
        w[s] = wgt;
    }
    __syncthreads();
    float acc = 0.f;
    const float* xb = x + (size_t)b * S_ * E_ + e;
    for (int s = 0; s < S_; s++) acc += w[s] * xb[(size_t)s * E_];
    out[(size_t)b * 3 * E_ + E_ + e]     = acc;
    out[(size_t)b * 3 * E_ + e]          = user_emb[(size_t)user_ids[b] * E_ + e];
    out[(size_t)b * 3 * E_ + 2 * E_ + e] = item_emb[(size_t)item_ids[b] * E_ + e];
}

// ---------------------------------------------------------------------------
// Scoring head v2: one block per sample b; outv[b] staged in smem once.
// 16 warps loop over the 600 targets.
// ---------------------------------------------------------------------------
__global__ __launch_bounds__(512)
void logits_kernel(const float* __restrict__ outv, const float* __restrict__ out_emb,
                   const int* __restrict__ pos_t, const int* __restrict__ pos_l,
                   const int* __restrict__ neg_t, const int* __restrict__ neg_l,
                   float* __restrict__ dout) {
    const int b    = blockIdx.x;
    const int t    = threadIdx.x;
    const int warp = t >> 5;
    const int lane = t & 31;
    __shared__ float ov[3 * E_];
    for (int i = t; i < 3 * E_; i += 512) ov[i] = outv[(size_t)b * 3 * E_ + i];
    __syncthreads();

    const int pl = pos_l[b];
    const int nl = neg_l[b];
    const float4* ovs = (const float4*)ov;

    for (int j = warp; j < NT_; j += 16) {
        int tgt; float valid, is_pos;
        if (j < P_) {
            tgt = pos_t[b * P_ + j];
            valid = (j < pl) ? 1.f : 0.f;
            is_pos = 1.f;
        } else {
            const int jn = j - P_;
            tgt = neg_t[b * N_ + jn];
            valid = (jn < nl) ? 1.f : 0.f;
            is_pos = 0.f;
        }
        const float4* er = (const float4*)(out_emb + (size_t)tgt * (3 * E_));
        float acc = 0.f;
#pragma unroll
        for (int i = 0; i < 6; i++) {
            const int k4 = lane + i * 32;
            float4 a = er[k4], c = ovs[k4];
            acc += a.x * c.x + a.y * c.y + a.z * c.z + a.w * c.w;
        }
#pragma unroll
        for (int o = 16; o; o >>= 1) acc += __shfl_xor_sync(0xffffffffu, acc, o);
        if (lane == 0) {
            const int idx = b * NT_ + j;
            dout[idx]                 = acc;
            dout[B_ * NT_ + idx]      = valid;
            dout[2 * B_ * NT_ + idx]  = is_pos * valid;
        }
    }
}

// ---------------------------------------------------------------------------
// Launch
// ---------------------------------------------------------------------------
extern "C" void kernel_launch(void* const* d_in, const int* in_sizes, int n_in,
                              void* d_out, int out_size) {
    const int*   attr           = (const int*)  d_in[0];
    const float* attr_tf        = (const float*)d_in[2];
    const float* attr_feat      = (const float*)d_in[3];
    const int*   attr_lens      = (const int*)  d_in[4];
    const int*   attr_lens_user = (const int*)  d_in[5];
    const int*   user_ids       = (const int*)  d_in[7];
    const int*   item_ids       = (const int*)  d_in[8];
    const int*   pos_targets    = (const int*)  d_in[9];
    const int*   pos_lens       = (const int*)  d_in[10];
    const int*   neg_targets    = (const int*)  d_in[11];
    const int*   neg_lens       = (const int*)  d_in[12];
    const float* attr_emb       = (const float*)d_in[13];
    const float* user_emb       = (const float*)d_in[14];
    const float* item_emb       = (const float*)d_in[15];
    const float* out_emb        = (const float*)d_in[16];
    const float* fw_W           = (const float*)d_in[17];
    const float* fw_b           = (const float*)d_in[18];
    const float* qkv_w          = (const float*)d_in[19];
    const float* qkv_b          = (const float*)d_in[20];
    const float* attn_out_w     = (const float*)d_in[21];
    const float* attn_out_b     = (const float*)d_in[22];
    const float* ln1_s          = (const float*)d_in[23];
    const float* ln1_b          = (const float*)d_in[24];
    const float* ff1_w          = (const float*)d_in[25];
    const float* ff1_b          = (const float*)d_in[26];
    const float* ff2_w          = (const float*)d_in[27];
    const float* ff2_b          = (const float*)d_in[28];
    const float* ln2_s          = (const float*)d_in[29];
    const float* ln2_b          = (const float*)d_in[30];

    float *x, *qkv, *attn, *tmp, *ff, *outv;
    cudaGetSymbolAddress((void**)&x,    g_x);
    cudaGetSymbolAddress((void**)&qkv,  g_qkv);
    cudaGetSymbolAddress((void**)&attn, g_attn);
    cudaGetSymbolAddress((void**)&tmp,  g_tmp);
    cudaGetSymbolAddress((void**)&ff,   g_ff);
    cudaGetSymbolAddress((void**)&outv, g_out);

    const int gemm_smem = STAGES * 2 * TSZ * (int)sizeof(float);   // 61440 B
    cudaFuncSetAttribute(tgemm<false>, cudaFuncAttributeMaxDynamicSharedMemorySize,
                         gemm_smem);
    cudaFuncSetAttribute(tgemm<true>, cudaFuncAttributeMaxDynamicSharedMemorySize,
                         gemm_smem);
    const int attn_smem = 2 * S_ * HD_ * (int)sizeof(float);       // 64KB
    cudaFuncSetAttribute(attn_kernel, cudaFuncAttributeMaxDynamicSharedMemorySize,
                         attn_smem);

    gather_kernel<<<(T_ * E_ / 4 + 255) / 256, 256>>>(attr, attr_emb, x);

    for (int l = 0; l < L_; l++) {
        const float* lqkv_w = qkv_w      + (size_t)l * 3 * E_ * E_;
        const float* lqkv_b = qkv_b      + (size_t)l * 3 * E_;
        const float* lao_w  = attn_out_w + (size_t)l * E_ * E_;
        const float* lao_b  = attn_out_b + (size_t)l * E_;
        const float* l1s    = ln1_s + (size_t)l * E_;
        const float* l1b    = ln1_b + (size_t)l * E_;
        const float* lf1_w  = ff1_w + (size_t)l * F_ * E_;
        const float* lf1_b  = ff1_b + (size_t)l * F_;
        const float* lf2_w  = ff2_w + (size_t)l * E_ * F_;
        const float* lf2_b  = ff2_b + (size_t)l * E_;
        const float* l2s    = ln2_s + (size_t)l * E_;
        const float* l2b    = ln2_b + (size_t)l * E_;

        tgemm<false><<<dim3(3 * E_ / 128, T_ / 128), 256, gemm_smem>>>(
            x, lqkv_w, lqkv_b, qkv, T_, 3 * E_, E_);
        attn_kernel<<<B_ * H_, S_, attn_smem>>>(qkv, attr_lens, attn);
        tgemm<false><<<dim3(E_ / 128, T_ / 128), 256, gemm_smem>>>(
            attn, lao_w, lao_b, tmp, T_, E_, E_);
        add_ln_kernel<<<T_ / 8, 256>>>(x, tmp, l1s, l1b, x);
        tgemm<true><<<dim3(F_ / 128, T_ / 128), 256, gemm_smem>>>(
            x, lf1_w, lf1_b, ff, T_, F_, E_);
        tgemm<false><<<dim3(E_ / 128, T_ / 128), 256, gemm_smem>>>(
            ff, lf2_w, lf2_b, tmp, T_, E_, F_);
        add_ln_kernel<<<T_ / 8, 256>>>(x, tmp, l2s, l2b, x);
    }

    pool_kernel<<<B_, 256>>>(x, attr_tf, attr_lens, attr_lens_user,
                             attr_feat, fw_W, fw_b,
                             user_ids, item_ids, user_emb, item_emb, outv);

    logits_kernel<<<B_, 512>>>(
        outv, out_emb, pos_targets, pos_lens, neg_targets, neg_lens,
        (float*)d_out);
}